// round 1
// baseline (speedup 1.0000x reference)
#include <cuda_runtime.h>
#include <math.h>

#define NQ 10
#define DIM 1024
#define NPAIR 45
#define TT 128
#define NTH 512
#define NL 3
#define NA 3
#define PI_F 3.14159265358979323846f

// Upper-triangle pair indices (i<j), row-major: 45 pairs for 10 qubits.
__constant__ int c_PI[NPAIR] = {0,0,0,0,0,0,0,0,0,
                                1,1,1,1,1,1,1,1,
                                2,2,2,2,2,2,2,
                                3,3,3,3,3,3,
                                4,4,4,4,4,
                                5,5,5,5,
                                6,6,6,
                                7,7,
                                8};
__constant__ int c_PJ[NPAIR] = {1,2,3,4,5,6,7,8,9,
                                2,3,4,5,6,7,8,9,
                                3,4,5,6,7,8,9,
                                4,5,6,7,8,9,
                                5,6,7,8,9,
                                6,7,8,9,
                                7,8,9,
                                8,9,
                                9};

__device__ __forceinline__ float2 cxmul(float2 a, float2 b) {
    return make_float2(a.x*b.x - a.y*b.y, a.x*b.y + a.y*b.x);
}
__device__ __forceinline__ float2 cxadd(float2 a, float2 b) {
    return make_float2(a.x + b.x, a.y + b.y);
}

__global__ __launch_bounds__(NTH)
void qh_kernel(const float* __restrict__ c_kt,
               const float* __restrict__ dc_kt,
               const float* __restrict__ vqc,
               const float* __restrict__ wproj,
               const float* __restrict__ bproj,
               const float* __restrict__ lalpha,
               float* __restrict__ out)
{
    __shared__ float feat[NQ * TT];      // [k][t], centered in place
    __shared__ float stR[DIM];
    __shared__ float stI[DIM];
    __shared__ float Jp[NPAIR];
    __shared__ int   pmask[NPAIR];
    __shared__ float meanv[NQ], stdv[NQ];
    __shared__ float cth[NQ], sth[NQ], phh[NQ];
    __shared__ float thetaS[NQ], phiS[NQ];
    __shared__ float2 gm[NL][NQ][4];     // 2x2 complex gate per (layer, qubit)
    __shared__ float wsh[NA][NQ];
    __shared__ float wred[16][4];

    const int b    = blockIdx.x;
    const int tid  = threadIdx.x;
    const int warp = tid >> 5;
    const int lane = tid & 31;

    const float* cb = c_kt  + (size_t)b * (NQ * TT);
    const float* db = dc_kt + (size_t)b * (NQ * TT);

    // ---- stage inputs: feat[k][t] = c + 0.5*delta (transposed into SMEM) ----
    for (int i = tid; i < NQ * TT; i += NTH) {
        int t = i / NQ, k = i - t * NQ;
        feat[k * TT + t] = fmaf(0.5f, db[i], cb[i]);
    }
    if (tid < NQ) {
        float th = cb[(TT - 1) * NQ + tid];
        float ph = db[(TT - 1) * NQ + tid];
        thetaS[tid] = th; phiS[tid] = ph;
        cth[tid] = cosf(0.5f * th);
        sth[tid] = sinf(0.5f * th);
        phh[tid] = 0.5f * ph;
    }
    if (tid < NPAIR)
        pmask[tid] = (1 << (NQ - 1 - c_PI[tid])) | (1 << (NQ - 1 - c_PJ[tid]));
    if (tid >= 64 && tid < 64 + NA * NQ) {
        int i = tid - 64;
        wsh[i / NQ][i - (i / NQ) * NQ] = wproj[i];
    }
    __syncthreads();

    // ---- means (warps 0-9) in parallel with gate-matrix build (threads 320+) ----
    if (warp < NQ) {
        float s = 0.f;
        for (int t = lane; t < TT; t += 32) s += feat[warp * TT + t];
        #pragma unroll
        for (int o = 16; o; o >>= 1) s += __shfl_xor_sync(0xffffffffu, s, o);
        if (lane == 0) meanv[warp] = s * (1.f / TT);
    } else if (tid >= 320 && tid < 320 + NL * NQ) {
        int idx = tid - 320;
        int l = idx / NQ, q = idx - l * NQ;
        float a  = vqc[idx * 3 + 0];
        float bb = vqc[idx * 3 + 1];
        float c  = vqc[idx * 3 + 2];
        // rot = RZ(c) RY(bb) RZ(a)
        float cb2 = cosf(0.5f * bb), sb2 = sinf(0.5f * bb);
        float apc = 0.5f * (a + c), amc = 0.5f * (a - c);
        float capc, sapc, camc, samc;
        sincosf(apc, &sapc, &capc);
        sincosf(amc, &samc, &camc);
        float2 u00 = make_float2( capc * cb2, -sapc * cb2);  //  e^{-i(a+c)/2} cos
        float2 u01 = make_float2(-camc * sb2, -samc * sb2);  // -e^{+i(a-c)/2} sin
        float2 u10 = make_float2( camc * sb2, -samc * sb2);  //  e^{-i(a-c)/2} sin
        float2 u11 = make_float2( capc * cb2,  sapc * cb2);  //  e^{+i(a+c)/2} cos
        if (l == 0) {
            gm[0][q][0] = u00; gm[0][q][1] = u01;
            gm[0][q][2] = u10; gm[0][q][3] = u11;
        } else {
            // Fold preceding intermediate RY(theta/2), RZ(phi/2) into this layer's rot:
            // M = rot * RZ(phi/2) * RY(theta/2);  _ry/_rz internal half-angles -> theta/4, phi/4.
            float thq = 0.25f * thetaS[q], phq = 0.25f * phiS[q];
            float ct = cosf(thq), st = sinf(thq);
            float cp, sp; sincosf(phq, &sp, &cp);
            float2 A00 = make_float2( cp * ct, -sp * ct);
            float2 A01 = make_float2(-cp * st,  sp * st);
            float2 A10 = make_float2( cp * st,  sp * st);
            float2 A11 = make_float2( cp * ct,  sp * ct);
            gm[l][q][0] = cxadd(cxmul(u00, A00), cxmul(u01, A10));
            gm[l][q][1] = cxadd(cxmul(u00, A01), cxmul(u01, A11));
            gm[l][q][2] = cxadd(cxmul(u10, A00), cxmul(u11, A10));
            gm[l][q][3] = cxadd(cxmul(u10, A01), cxmul(u11, A11));
        }
    }
    __syncthreads();

    // ---- center ----
    for (int i = tid; i < NQ * TT; i += NTH)
        feat[i] -= meanv[i >> 7];
    __syncthreads();

    // ---- std ----
    if (warp < NQ) {
        float s = 0.f;
        for (int t = lane; t < TT; t += 32) {
            float v = feat[warp * TT + t];
            s = fmaf(v, v, s);
        }
        #pragma unroll
        for (int o = 16; o; o >>= 1) s += __shfl_xor_sync(0xffffffffu, s, o);
        if (lane == 0) stdv[warp] = fmaxf(sqrtf(s * (1.f / (TT - 1))), 1e-8f);
    }
    __syncthreads();

    // ---- pair correlations -> J ----
    {
        float ea = expf(lalpha[0]);
        for (int p = warp; p < NPAIR; p += 16) {
            int i = c_PI[p], j = c_PJ[p];
            float s = 0.f;
            for (int t = lane; t < TT; t += 32)
                s = fmaf(feat[i * TT + t], feat[j * TT + t], s);
            #pragma unroll
            for (int o = 16; o; o >>= 1) s += __shfl_xor_sync(0xffffffffu, s, o);
            if (lane == 0) {
                float rho = s / ((float)(TT - 1) * stdv[i] * stdv[j]);
                Jp[p] = tanhf(rho * ea);
            }
        }
    }
    __syncthreads();

    // ---- build initial product state + fused entangling phase ----
    #pragma unroll
    for (int r = 0; r < 2; r++) {
        int s = tid + r * NTH;
        float mag = 1.f, phase = 0.f;
        #pragma unroll
        for (int q = 0; q < NQ; q++) {
            bool bit = (s >> (NQ - 1 - q)) & 1;
            mag   *= bit ?  sth[q] :  cth[q];
            phase += bit ?  phh[q] : -phh[q];
        }
        float aJ = 0.f;
        #pragma unroll
        for (int p = 0; p < NPAIR; p++) {
            bool par = __popc(s & pmask[p]) & 1;
            aJ += par ? Jp[p] : -Jp[p];
        }
        phase = fmaf(0.5f * PI_F, aJ, phase);
        float sp, cp; sincosf(phase, &sp, &cp);
        stR[s] = mag * cp;
        stI[s] = mag * sp;
    }

    // ---- VQC layers: 10 butterflies + 1 composed-CNOT permutation each ----
    #pragma unroll
    for (int l = 0; l < NL; l++) {
        #pragma unroll
        for (int q = 0; q < NQ; q++) {
            __syncthreads();
            const int bpos = NQ - 1 - q;
            const int m = 1 << bpos;
            int s0 = ((tid >> bpos) << (bpos + 1)) | (tid & (m - 1));
            int s1 = s0 | m;
            float2 u00 = gm[l][q][0], u01 = gm[l][q][1];
            float2 u10 = gm[l][q][2], u11 = gm[l][q][3];
            float a0r = stR[s0], a0i = stI[s0];
            float a1r = stR[s1], a1i = stI[s1];
            float n0r = u00.x*a0r - u00.y*a0i + u01.x*a1r - u01.y*a1i;
            float n0i = u00.x*a0i + u00.y*a0r + u01.x*a1i + u01.y*a1r;
            float n1r = u10.x*a0r - u10.y*a0i + u11.x*a1r - u11.y*a1i;
            float n1i = u10.x*a0i + u10.y*a0r + u11.x*a1i + u11.y*a1r;
            stR[s0] = n0r; stI[s0] = n0i;
            stR[s1] = n1r; stI[s1] = n1i;
        }
        // Composed permutation: final[s] = old[P_0(P_1(...P_9(s)))], rng = l+1
        __syncthreads();
        const int rng = l + 1;
        int iA = tid, iB = tid + NTH;
        #pragma unroll
        for (int q = NQ - 1; q >= 0; q--) {
            int tgt = q + rng; if (tgt >= NQ) tgt -= NQ;
            const int tb = 1 << (NQ - 1 - tgt);
            if ((iA >> (NQ - 1 - q)) & 1) iA ^= tb;
            if ((iB >> (NQ - 1 - q)) & 1) iB ^= tb;
        }
        float rA = stR[iA], mA = stI[iA];
        float rB = stR[iB], mB = stI[iB];
        __syncthreads();
        stR[tid]       = rA; stI[tid]       = mA;
        stR[tid + NTH] = rB; stI[tid + NTH] = mB;
    }
    __syncthreads();

    // ---- epilogue: out[a] = sum_s |amp_s|^2 * sum_k sign_k(s) w[a][k] + b[a] ----
    float acc0 = 0.f, acc1 = 0.f, acc2 = 0.f;
    #pragma unroll
    for (int r = 0; r < 2; r++) {
        int s = tid + r * NTH;
        float re = stR[s], im = stI[s];
        float pr = re * re + im * im;
        float g0 = 0.f, g1 = 0.f, g2 = 0.f;
        #pragma unroll
        for (int k = 0; k < NQ; k++) {
            float sg = ((s >> (NQ - 1 - k)) & 1) ? -1.f : 1.f;
            g0 = fmaf(sg, wsh[0][k], g0);
            g1 = fmaf(sg, wsh[1][k], g1);
            g2 = fmaf(sg, wsh[2][k], g2);
        }
        acc0 = fmaf(pr, g0, acc0);
        acc1 = fmaf(pr, g1, acc1);
        acc2 = fmaf(pr, g2, acc2);
    }
    #pragma unroll
    for (int o = 16; o; o >>= 1) {
        acc0 += __shfl_xor_sync(0xffffffffu, acc0, o);
        acc1 += __shfl_xor_sync(0xffffffffu, acc1, o);
        acc2 += __shfl_xor_sync(0xffffffffu, acc2, o);
    }
    if (lane == 0) {
        wred[warp][0] = acc0; wred[warp][1] = acc1; wred[warp][2] = acc2;
    }
    __syncthreads();
    if (tid < NA) {
        float s = bproj[tid];
        #pragma unroll
        for (int w = 0; w < 16; w++) s += wred[w][tid];
        out[b * NA + tid] = s;
    }
}

extern "C" void kernel_launch(void* const* d_in, const int* in_sizes, int n_in,
                              void* d_out, int out_size) {
    const float* c_kt   = (const float*)d_in[0];
    const float* dc_kt  = (const float*)d_in[1];
    const float* vqc    = (const float*)d_in[2];
    const float* wproj  = (const float*)d_in[3];
    const float* bproj  = (const float*)d_in[4];
    const float* lalpha = (const float*)d_in[5];
    int B = in_sizes[0] / (NQ * TT);
    qh_kernel<<<B, NTH>>>(c_kt, dc_kt, vqc, wproj, bproj, lalpha, (float*)d_out);
}

// round 2
// speedup vs baseline: 2.3738x; 2.3738x over previous
#include <cuda_runtime.h>
#include <math.h>

#define NQ 10
#define DIM 1024
#define NPAIR 45
#define TT 128
#define NTH 256
#define NL 3
#define NA 3
#define PI_F 3.14159265358979323846f

// Upper-triangle pair indices (i<j), row-major: 45 pairs for 10 qubits.
__constant__ int c_PI[NPAIR] = {0,0,0,0,0,0,0,0,0, 1,1,1,1,1,1,1,1, 2,2,2,2,2,2,2,
                                3,3,3,3,3,3, 4,4,4,4,4, 5,5,5,5, 6,6,6, 7,7, 8};
__constant__ int c_PJ[NPAIR] = {1,2,3,4,5,6,7,8,9, 2,3,4,5,6,7,8,9, 3,4,5,6,7,8,9,
                                4,5,6,7,8,9, 5,6,7,8,9, 6,7,8,9, 7,8,9, 8,9, 9};

__device__ __forceinline__ float2 cxmul(float2 a, float2 b) {
    return make_float2(a.x*b.x - a.y*b.y, a.x*b.y + a.y*b.x);
}
__device__ __forceinline__ float2 cxadd(float2 a, float2 b) {
    return make_float2(a.x + b.x, a.y + b.y);
}

// In-register butterfly on one amplitude pair.
__device__ __forceinline__ void bf_pair(const float2* u,
                                        float& r0, float& i0, float& r1, float& i1) {
    float n0r = u[0].x*r0 - u[0].y*i0 + u[1].x*r1 - u[1].y*i1;
    float n0i = u[0].x*i0 + u[0].y*r0 + u[1].x*i1 + u[1].y*r1;
    float n1r = u[2].x*r0 - u[2].y*i0 + u[3].x*r1 - u[3].y*i1;
    float n1i = u[2].x*i0 + u[2].y*r0 + u[3].x*i1 + u[3].y*r1;
    r0 = n0r; i0 = n0i; r1 = n1r; i1 = n1i;
}

// Shuffle butterfly on lane bit k (all 4 register amps).
__device__ __forceinline__ void lane_gate(const float2* u, int k, int lane,
                                          float aR[4], float aI[4]) {
    bool b = (lane >> k) & 1;
    float2 um = b ? u[3] : u[0];   // coefficient of my amp
    float2 uo = b ? u[2] : u[1];   // coefficient of partner amp
    #pragma unroll
    for (int r = 0; r < 4; r++) {
        float pr = __shfl_xor_sync(0xffffffffu, aR[r], 1 << k);
        float pi = __shfl_xor_sync(0xffffffffu, aI[r], 1 << k);
        float nr = um.x*aR[r] - um.y*aI[r] + uo.x*pr - uo.y*pi;
        float ni = um.x*aI[r] + um.y*aR[r] + uo.x*pi + uo.y*pr;
        aR[r] = nr; aI[r] = ni;
    }
}

__device__ __forceinline__ int physidx(int s) { return s + (s >> 5); }
// View-B mapping: swap amp bits [9:7] <-> slot bits [2:0]
__device__ __forceinline__ int sigma(int j) {
    return (j & 0x078) | ((j & 7) << 7) | (j >> 7);
}

__global__ __launch_bounds__(NTH, 3)
void qh_kernel(const float* __restrict__ c_kt,
               const float* __restrict__ dc_kt,
               const float* __restrict__ vqc,
               const float* __restrict__ wproj,
               const float* __restrict__ bproj,
               const float* __restrict__ lalpha,
               float* __restrict__ out)
{
    __shared__ float feat[NQ * TT];           // [k][t], centered in place
    __shared__ float sR[DIM + (DIM >> 5)];    // padded state (re)
    __shared__ float sI[DIM + (DIM >> 5)];    // padded state (im)
    __shared__ float Jp[NPAIR];
    __shared__ float meanv[NQ], stdv[NQ];
    __shared__ float cth[NQ], sth[NQ], phh[NQ];
    __shared__ float thetaS[NQ], phiS[NQ];
    __shared__ float2 gm[NL][NQ][4];
    __shared__ float wsh[NA][NQ];
    __shared__ float wred[8][4];

    const int b    = blockIdx.x;
    const int tid  = threadIdx.x;
    const int warp = tid >> 5;
    const int lane = tid & 31;

    const float* cb = c_kt  + (size_t)b * (NQ * TT);
    const float* db = dc_kt + (size_t)b * (NQ * TT);

    // ---- stage inputs ----
    for (int i = tid; i < NQ * TT; i += NTH) {
        int t = i / NQ, k = i - t * NQ;
        feat[k * TT + t] = fmaf(0.5f, db[i], cb[i]);
    }
    if (tid < NQ) {
        float th = cb[(TT - 1) * NQ + tid];
        float ph = db[(TT - 1) * NQ + tid];
        thetaS[tid] = th; phiS[tid] = ph;
        cth[tid] = cosf(0.5f * th);
        sth[tid] = sinf(0.5f * th);
        phh[tid] = 0.5f * ph;
    }
    if (tid >= 32 && tid < 32 + NA * NQ) {
        int i = tid - 32;
        wsh[i / NQ][i - (i / NQ) * NQ] = wproj[i];
    }
    __syncthreads();

    // ---- means on warps 1-7; gate-matrix build on warp 0 (lanes 0-29) ----
    if (warp >= 1) {
        for (int k = warp - 1; k < NQ; k += 7) {
            float s = 0.f;
            for (int t = lane; t < TT; t += 32) s += feat[k * TT + t];
            #pragma unroll
            for (int o = 16; o; o >>= 1) s += __shfl_xor_sync(0xffffffffu, s, o);
            if (lane == 0) meanv[k] = s * (1.f / TT);
        }
    } else if (tid < NL * NQ) {
        int l = tid / NQ, q = tid - l * NQ;
        float a  = vqc[tid * 3 + 0];
        float bb = vqc[tid * 3 + 1];
        float c  = vqc[tid * 3 + 2];
        float cb2 = cosf(0.5f * bb), sb2 = sinf(0.5f * bb);
        float apc = 0.5f * (a + c), amc = 0.5f * (a - c);
        float capc, sapc, camc, samc;
        sincosf(apc, &sapc, &capc);
        sincosf(amc, &samc, &camc);
        float2 u00 = make_float2( capc * cb2, -sapc * cb2);
        float2 u01 = make_float2(-camc * sb2, -samc * sb2);
        float2 u10 = make_float2( camc * sb2, -samc * sb2);
        float2 u11 = make_float2( capc * cb2,  sapc * cb2);
        if (l == 0) {
            gm[0][q][0] = u00; gm[0][q][1] = u01;
            gm[0][q][2] = u10; gm[0][q][3] = u11;
        } else {
            // Fold preceding RY(theta/2), RZ(phi/2) into this layer's rot.
            float thq = 0.25f * thetaS[q], phq = 0.25f * phiS[q];
            float ct = cosf(thq), st = sinf(thq);
            float cp, sp; sincosf(phq, &sp, &cp);
            float2 A00 = make_float2( cp * ct, -sp * ct);
            float2 A01 = make_float2(-cp * st,  sp * st);
            float2 A10 = make_float2( cp * st,  sp * st);
            float2 A11 = make_float2( cp * ct,  sp * ct);
            gm[l][q][0] = cxadd(cxmul(u00, A00), cxmul(u01, A10));
            gm[l][q][1] = cxadd(cxmul(u00, A01), cxmul(u01, A11));
            gm[l][q][2] = cxadd(cxmul(u10, A00), cxmul(u11, A10));
            gm[l][q][3] = cxadd(cxmul(u10, A01), cxmul(u11, A11));
        }
    }
    __syncthreads();

    // ---- center ----
    for (int i = tid; i < NQ * TT; i += NTH)
        feat[i] -= meanv[i >> 7];
    __syncthreads();

    // ---- std ----
    for (int k = warp; k < NQ; k += 8) {
        float s = 0.f;
        for (int t = lane; t < TT; t += 32) {
            float v = feat[k * TT + t];
            s = fmaf(v, v, s);
        }
        #pragma unroll
        for (int o = 16; o; o >>= 1) s += __shfl_xor_sync(0xffffffffu, s, o);
        if (lane == 0) stdv[k] = fmaxf(sqrtf(s * (1.f / (TT - 1))), 1e-8f);
    }
    __syncthreads();

    // ---- pair correlations -> J ----
    {
        float ea = expf(lalpha[0]);
        for (int p = warp; p < NPAIR; p += 8) {
            int i = c_PI[p], j = c_PJ[p];
            float s = 0.f;
            for (int t = lane; t < TT; t += 32)
                s = fmaf(feat[i * TT + t], feat[j * TT + t], s);
            #pragma unroll
            for (int o = 16; o; o >>= 1) s += __shfl_xor_sync(0xffffffffu, s, o);
            if (lane == 0) {
                float rho = s / ((float)(TT - 1) * stdv[i] * stdv[j]);
                Jp[p] = tanhf(rho * ea);
            }
        }
    }
    __syncthreads();

    // ===================== state in registers =====================
    // slot s = (tid<<2) | r.  amp bit p=9-q:  q in 0..7 <-> tid bit (7-q);
    // q8 <-> r bit1, q9 <-> r bit0.
    float aR[4], aI[4];
    {
        // hi-product (qubits 0..7), shared across the 4 register amps
        float magHi = 1.f, phHi = 0.f;
        #pragma unroll
        for (int q = 0; q < 8; q++) {
            bool t = (tid >> (7 - q)) & 1;
            magHi *= t ? sth[q] : cth[q];
            phHi  += t ? phh[q] : -phh[q];
        }
        // entangling phase: split pairs into hi-hi / hi-q8 / hi-q9 / (q8,q9)
        float base = 0.f, A = 0.f, Bv = 0.f;
        int idx = 0;
        #pragma unroll
        for (int i = 0; i < 9; i++) {
            #pragma unroll
            for (int j = i + 1; j < 10; j++) {
                if (i < 8) {
                    bool ti = (tid >> (7 - i)) & 1;
                    float Jv = Jp[idx];
                    if (j < 8) {
                        bool tj = (tid >> (7 - j)) & 1;
                        base += (ti ^ tj) ? Jv : -Jv;
                    } else if (j == 8) {
                        A += ti ? Jv : -Jv;
                    } else {
                        Bv += ti ? Jv : -Jv;
                    }
                }
                idx++;
            }
        }
        float C = Jp[44];
        float c8 = cth[8], s8 = sth[8], c9 = cth[9], s9 = sth[9];
        float p8 = phh[8], p9 = phh[9];
        #pragma unroll
        for (int r = 0; r < 4; r++) {
            bool b8 = (r >> 1) & 1, b9 = r & 1;
            float mag = magHi * (b8 ? s8 : c8) * (b9 ? s9 : c9);
            float ph  = phHi + (b8 ? p8 : -p8) + (b9 ? p9 : -p9);
            float aJ  = base + (b8 ? -A : A) + (b9 ? -Bv : Bv)
                      + ((b8 ^ b9) ? C : -C);
            ph = fmaf(0.5f * PI_F, aJ, ph);
            float sp, cp; sincosf(ph, &sp, &cp);
            aR[r] = mag * cp; aI[r] = mag * sp;
        }
    }

    float2 u[4];
    #pragma unroll
    for (int l = 0; l < NL; l++) {
        // register gates: q=9 (r bit0), q=8 (r bit1)
        u[0]=gm[l][9][0]; u[1]=gm[l][9][1]; u[2]=gm[l][9][2]; u[3]=gm[l][9][3];
        bf_pair(u, aR[0], aI[0], aR[1], aI[1]);
        bf_pair(u, aR[2], aI[2], aR[3], aI[3]);
        u[0]=gm[l][8][0]; u[1]=gm[l][8][1]; u[2]=gm[l][8][2]; u[3]=gm[l][8][3];
        bf_pair(u, aR[0], aI[0], aR[2], aI[2]);
        bf_pair(u, aR[1], aI[1], aR[3], aI[3]);
        // lane gates: q=7..3  (lane bit k = 7-q)
        #pragma unroll
        for (int q = 7; q >= 3; q--) {
            u[0]=gm[l][q][0]; u[1]=gm[l][q][1]; u[2]=gm[l][q][2]; u[3]=gm[l][q][3];
            lane_gate(u, 7 - q, lane, aR, aI);
        }
        // exchange to view B (swap amp[9:7] <-> slot[2:0])
        __syncthreads();
        #pragma unroll
        for (int r = 0; r < 4; r++) {
            int s = (tid << 2) | r; int p = physidx(s);
            sR[p] = aR[r]; sI[p] = aI[r];
        }
        __syncthreads();
        #pragma unroll
        for (int r = 0; r < 4; r++) {
            int j = (tid << 2) | r; int p = physidx(sigma(j));
            aR[r] = sR[p]; aI[r] = sI[p];
        }
        // view-B gates: q=2 -> slot bit0, q=1 -> slot bit1, q=0 -> lane bit0
        u[0]=gm[l][2][0]; u[1]=gm[l][2][1]; u[2]=gm[l][2][2]; u[3]=gm[l][2][3];
        bf_pair(u, aR[0], aI[0], aR[1], aI[1]);
        bf_pair(u, aR[2], aI[2], aR[3], aI[3]);
        u[0]=gm[l][1][0]; u[1]=gm[l][1][1]; u[2]=gm[l][1][2]; u[3]=gm[l][1][3];
        bf_pair(u, aR[0], aI[0], aR[2], aI[2]);
        bf_pair(u, aR[1], aI[1], aR[3], aI[3]);
        u[0]=gm[l][0][0]; u[1]=gm[l][0][1]; u[2]=gm[l][0][2]; u[3]=gm[l][0][3];
        lane_gate(u, 0, lane, aR, aI);
        // exchange back to view A, fused with the composed-CNOT permutation
        __syncthreads();
        #pragma unroll
        for (int r = 0; r < 4; r++) {
            int j = (tid << 2) | r; int p = physidx(sigma(j));
            sR[p] = aR[r]; sI[p] = aI[r];
        }
        __syncthreads();
        const int rng = l + 1;
        #pragma unroll
        for (int r = 0; r < 4; r++) {
            int idx = (tid << 2) | r;
            #pragma unroll
            for (int q = NQ - 1; q >= 0; q--) {
                int tgt = q + rng; if (tgt >= NQ) tgt -= NQ;
                if ((idx >> (NQ - 1 - q)) & 1) idx ^= 1 << (NQ - 1 - tgt);
            }
            int p = physidx(idx);
            aR[r] = sR[p]; aI[r] = sI[p];
        }
    }

    // ---- epilogue ----
    float g0Hi = 0.f, g1Hi = 0.f, g2Hi = 0.f;
    #pragma unroll
    for (int k = 0; k < 8; k++) {
        float sg = ((tid >> (7 - k)) & 1) ? -1.f : 1.f;
        g0Hi = fmaf(sg, wsh[0][k], g0Hi);
        g1Hi = fmaf(sg, wsh[1][k], g1Hi);
        g2Hi = fmaf(sg, wsh[2][k], g2Hi);
    }
    float w08 = wsh[0][8], w09 = wsh[0][9];
    float w18 = wsh[1][8], w19 = wsh[1][9];
    float w28 = wsh[2][8], w29 = wsh[2][9];
    float acc0 = 0.f, acc1 = 0.f, acc2 = 0.f;
    #pragma unroll
    for (int r = 0; r < 4; r++) {
        bool b8 = (r >> 1) & 1, b9 = r & 1;
        float pr = aR[r]*aR[r] + aI[r]*aI[r];
        acc0 = fmaf(pr, g0Hi + (b8 ? -w08 : w08) + (b9 ? -w09 : w09), acc0);
        acc1 = fmaf(pr, g1Hi + (b8 ? -w18 : w18) + (b9 ? -w19 : w19), acc1);
        acc2 = fmaf(pr, g2Hi + (b8 ? -w28 : w28) + (b9 ? -w29 : w29), acc2);
    }
    #pragma unroll
    for (int o = 16; o; o >>= 1) {
        acc0 += __shfl_xor_sync(0xffffffffu, acc0, o);
        acc1 += __shfl_xor_sync(0xffffffffu, acc1, o);
        acc2 += __shfl_xor_sync(0xffffffffu, acc2, o);
    }
    if (lane == 0) {
        wred[warp][0] = acc0; wred[warp][1] = acc1; wred[warp][2] = acc2;
    }
    __syncthreads();
    if (tid < NA) {
        float s = bproj[tid];
        #pragma unroll
        for (int w = 0; w < 8; w++) s += wred[w][tid];
        out[b * NA + tid] = s;
    }
}

extern "C" void kernel_launch(void* const* d_in, const int* in_sizes, int n_in,
                              void* d_out, int out_size) {
    const float* c_kt   = (const float*)d_in[0];
    const float* dc_kt  = (const float*)d_in[1];
    const float* vqc    = (const float*)d_in[2];
    const float* wproj  = (const float*)d_in[3];
    const float* bproj  = (const float*)d_in[4];
    const float* lalpha = (const float*)d_in[5];
    int B = in_sizes[0] / (NQ * TT);
    qh_kernel<<<B, NTH>>>(c_kt, dc_kt, vqc, wproj, bproj, lalpha, (float*)d_out);
}

// round 3
// speedup vs baseline: 2.9171x; 1.2289x over previous
#include <cuda_runtime.h>
#include <math.h>

#define NQ 10
#define DIM 1024
#define NPAIR 45
#define NG 55
#define NTASK 65
#define TT 128
#define NTH 256
#define NL 3
#define NA 3
#define PI_F 3.14159265358979323846f

// Upper-triangle (i<j) pair indices, row-major: 45 pairs.
__constant__ int c_PI[NPAIR] = {0,0,0,0,0,0,0,0,0, 1,1,1,1,1,1,1,1, 2,2,2,2,2,2,2,
                                3,3,3,3,3,3, 4,4,4,4,4, 5,5,5,5, 6,6,6, 7,7, 8};
__constant__ int c_PJ[NPAIR] = {1,2,3,4,5,6,7,8,9, 2,3,4,5,6,7,8,9, 3,4,5,6,7,8,9,
                                4,5,6,7,8,9, 5,6,7,8,9, 6,7,8,9, 7,8,9, 8,9, 9};
// Gram tasks: all (i<=j) pairs incl diagonal, row-major: 55.
__constant__ int c_TI[NG] = {0,0,0,0,0,0,0,0,0,0, 1,1,1,1,1,1,1,1,1, 2,2,2,2,2,2,2,2,
                             3,3,3,3,3,3,3, 4,4,4,4,4,4, 5,5,5,5,5, 6,6,6,6, 7,7,7, 8,8, 9};
__constant__ int c_TJ[NG] = {0,1,2,3,4,5,6,7,8,9, 1,2,3,4,5,6,7,8,9, 2,3,4,5,6,7,8,9,
                             3,4,5,6,7,8,9, 4,5,6,7,8,9, 5,6,7,8,9, 6,7,8,9, 7,8,9, 8,9, 9};
// Offset of (i,i) within the 55-list.
__constant__ int c_OFF[NQ] = {0,10,19,27,34,40,45,49,52,54};

__device__ __forceinline__ float2 cxmul(float2 a, float2 b) {
    return make_float2(a.x*b.x - a.y*b.y, a.x*b.y + a.y*b.x);
}
__device__ __forceinline__ float2 cxadd(float2 a, float2 b) {
    return make_float2(a.x + b.x, a.y + b.y);
}

// Butterfly on one amplitude pair; A=(u00,u01), B=(u10,u11) packed float4.
__device__ __forceinline__ void bf_pair(float4 A, float4 B,
                                        float& r0, float& i0, float& r1, float& i1) {
    float n0r = A.x*r0 - A.y*i0 + A.z*r1 - A.w*i1;
    float n0i = A.x*i0 + A.y*r0 + A.z*i1 + A.w*r1;
    float n1r = B.x*r0 - B.y*i0 + B.z*r1 - B.w*i1;
    float n1i = B.x*i0 + B.y*r0 + B.z*i1 + B.w*r1;
    r0 = n0r; i0 = n0i; r1 = n1r; i1 = n1i;
}

// Shuffle butterfly on lane bit k for all 4 register amps.
__device__ __forceinline__ void lane_gate(float4 A, float4 B, int k, int lane,
                                          float aR[4], float aI[4]) {
    bool bb = (lane >> k) & 1;
    float umx = bb ? B.z : A.x, umy = bb ? B.w : A.y;
    float uox = bb ? B.x : A.z, uoy = bb ? B.y : A.w;
    #pragma unroll
    for (int r = 0; r < 4; r++) {
        float pr = __shfl_xor_sync(0xffffffffu, aR[r], 1 << k);
        float pi = __shfl_xor_sync(0xffffffffu, aI[r], 1 << k);
        float nr = umx*aR[r] - umy*aI[r] + uox*pr - uoy*pi;
        float ni = umx*aI[r] + umy*aR[r] + uox*pi + uoy*pr;
        aR[r] = nr; aI[r] = ni;
    }
}

// View-B map: swap amp bits [9:7] <-> slot bits [2:0] (involution).
__device__ __forceinline__ int sigma(int j) {
    return (j & 0x078) | ((j & 7) << 7) | (j >> 7);
}
// r-major shared addressing for amplitude/slot index s.
__device__ __forceinline__ int ADDR(int s) { return ((s & 3) << 8) | (s >> 2); }

__global__ __launch_bounds__(NTH, 4)
void qh_kernel(const float* __restrict__ c_kt,
               const float* __restrict__ dc_kt,
               const float* __restrict__ vqc,
               const float* __restrict__ wproj,
               const float* __restrict__ bproj,
               const float* __restrict__ lalpha,
               float* __restrict__ out)
{
    __shared__ float feat[NQ * TT];     // [k][t]
    __shared__ float sR[DIM];
    __shared__ float sI[DIM];
    __shared__ float G[NG];
    __shared__ float Ssum[NQ];
    __shared__ float Jp[NPAIR];
    __shared__ float cth[NQ], sth[NQ], phh[NQ];
    __shared__ float thetaS[NQ], phiS[NQ];
    __shared__ float4 gm4[NL][NQ][2];
    __shared__ float wsh[NA][NQ];
    __shared__ float wred[8][4];

    const int b    = blockIdx.x;
    const int tid  = threadIdx.x;
    const int warp = tid >> 5;
    const int lane = tid & 31;

    const float* cb = c_kt  + (size_t)b * (NQ * TT);
    const float* db = dc_kt + (size_t)b * (NQ * TT);

    // ---- phase 1: stage inputs ----
    for (int i = tid; i < NQ * TT; i += NTH) {
        int t = i / NQ, k = i - t * NQ;
        feat[k * TT + t] = fmaf(0.5f, db[i], cb[i]);
    }
    if (tid < NQ) {
        thetaS[tid] = cb[(TT - 1) * NQ + tid];
        phiS[tid]   = db[(TT - 1) * NQ + tid];
    }
    if (tid >= 32 && tid < 32 + NA * NQ) {
        int i = tid - 32;
        wsh[i / NQ][i - (i / NQ) * NQ] = wproj[i];
    }
    __syncthreads();

    // ---- phase 2: 55 Gram dots + 10 row sums, one pass ----
    for (int tk = warp; tk < NTASK; tk += 8) {
        float s = 0.f;
        if (tk < NG) {
            const float* fi = feat + c_TI[tk] * TT;
            const float* fj = feat + c_TJ[tk] * TT;
            #pragma unroll
            for (int m = 0; m < 4; m++) {
                int t = lane + m * 32;
                s = fmaf(fi[t], fj[t], s);
            }
        } else {
            const float* fi = feat + (tk - NG) * TT;
            #pragma unroll
            for (int m = 0; m < 4; m++) s += fi[lane + m * 32];
        }
        #pragma unroll
        for (int o = 16; o; o >>= 1) s += __shfl_xor_sync(0xffffffffu, s, o);
        if (lane == 0) {
            if (tk < NG) G[tk] = s; else Ssum[tk - NG] = s;
        }
    }
    __syncthreads();

    // ---- phase 3 (parallel sub-jobs) ----
    if (tid < NPAIR) {
        // J couplings
        int i = c_PI[tid], j = c_PJ[tid];
        float Si = Ssum[i], Sj = Ssum[j];
        const float invT = 1.f / TT, invT1 = 1.f / (TT - 1);
        float vi = (G[c_OFF[i]] - Si * Si * invT) * invT1;
        float vj = (G[c_OFF[j]] - Sj * Sj * invT) * invT1;
        float si = fmaxf(sqrtf(vi), 1e-8f);
        float sj = fmaxf(sqrtf(vj), 1e-8f);
        float num = (G[c_OFF[i] + (j - i)] - Si * Sj * invT) * invT1;
        float rho = num / (si * sj);
        Jp[tid] = __tanhf(rho * __expf(lalpha[0]));
    } else if (tid >= 64 && tid < 64 + NQ) {
        int q = tid - 64;
        float th = thetaS[q];
        cth[q] = cosf(0.5f * th);
        sth[q] = sinf(0.5f * th);
        phh[q] = 0.5f * phiS[q];
    } else if (tid >= 128 && tid < 128 + NL * NQ) {
        int idx = tid - 128;
        int l = idx / NQ, q = idx - l * NQ;
        float a  = vqc[idx * 3 + 0];
        float bb = vqc[idx * 3 + 1];
        float c  = vqc[idx * 3 + 2];
        float cb2 = cosf(0.5f * bb), sb2 = sinf(0.5f * bb);
        float apc = 0.5f * (a + c), amc = 0.5f * (a - c);
        float capc, sapc, camc, samc;
        sincosf(apc, &sapc, &capc);
        sincosf(amc, &samc, &camc);
        float2 u00 = make_float2( capc * cb2, -sapc * cb2);
        float2 u01 = make_float2(-camc * sb2, -samc * sb2);
        float2 u10 = make_float2( camc * sb2, -samc * sb2);
        float2 u11 = make_float2( capc * cb2,  sapc * cb2);
        if (l != 0) {
            // Fold preceding RY(theta/2), RZ(phi/2) into this layer's rot.
            float thq = 0.25f * thetaS[q], phq = 0.25f * phiS[q];
            float ct = cosf(thq), st = sinf(thq);
            float cp, sp; sincosf(phq, &sp, &cp);
            float2 A00 = make_float2( cp * ct, -sp * ct);
            float2 A01 = make_float2(-cp * st,  sp * st);
            float2 A10 = make_float2( cp * st,  sp * st);
            float2 A11 = make_float2( cp * ct,  sp * ct);
            float2 v00 = cxadd(cxmul(u00, A00), cxmul(u01, A10));
            float2 v01 = cxadd(cxmul(u00, A01), cxmul(u01, A11));
            float2 v10 = cxadd(cxmul(u10, A00), cxmul(u11, A10));
            float2 v11 = cxadd(cxmul(u10, A01), cxmul(u11, A11));
            u00 = v00; u01 = v01; u10 = v10; u11 = v11;
        }
        gm4[l][q][0] = make_float4(u00.x, u00.y, u01.x, u01.y);
        gm4[l][q][1] = make_float4(u10.x, u10.y, u11.x, u11.y);
    }
    __syncthreads();

    // ===================== state in registers =====================
    // slot s = (tid<<2)|r.  qubit q in 0..7 <-> tid bit (7-q); q8 <-> r bit1, q9 <-> r bit0.
    float aR[4], aI[4];
    {
        float magHi = 1.f, phHi = 0.f;
        #pragma unroll
        for (int q = 0; q < 8; q++) {
            bool t = (tid >> (7 - q)) & 1;
            magHi *= t ? sth[q] : cth[q];
            phHi  += t ? phh[q] : -phh[q];
        }
        float base = 0.f, A = 0.f, Bv = 0.f;
        int idx = 0;
        #pragma unroll
        for (int i = 0; i < 9; i++) {
            #pragma unroll
            for (int j = i + 1; j < 10; j++) {
                if (i < 8) {
                    bool ti = (tid >> (7 - i)) & 1;
                    float Jv = Jp[idx];
                    if (j < 8) {
                        bool tj = (tid >> (7 - j)) & 1;
                        base += (ti ^ tj) ? Jv : -Jv;
                    } else if (j == 8) {
                        A += ti ? Jv : -Jv;
                    } else {
                        Bv += ti ? Jv : -Jv;
                    }
                }
                idx++;
            }
        }
        float C = Jp[44];
        float c8 = cth[8], s8 = sth[8], c9 = cth[9], s9 = sth[9];
        float p8 = phh[8], p9 = phh[9];
        #pragma unroll
        for (int r = 0; r < 4; r++) {
            bool b8 = (r >> 1) & 1, b9 = r & 1;
            float mag = magHi * (b8 ? s8 : c8) * (b9 ? s9 : c9);
            float ph  = phHi + (b8 ? p8 : -p8) + (b9 ? p9 : -p9);
            float aJ  = base + (b8 ? -A : A) + (b9 ? -Bv : Bv) + ((b8 ^ b9) ? C : -C);
            ph = fmaf(0.5f * PI_F, aJ, ph);
            float sp, cp; __sincosf(ph, &sp, &cp);
            aR[r] = mag * cp; aI[r] = mag * sp;
        }
    }

    #pragma unroll
    for (int l = 0; l < NL; l++) {
        // register gates q=9 (r bit0), q=8 (r bit1)
        {
            float4 A = gm4[l][9][0], B = gm4[l][9][1];
            bf_pair(A, B, aR[0], aI[0], aR[1], aI[1]);
            bf_pair(A, B, aR[2], aI[2], aR[3], aI[3]);
        }
        {
            float4 A = gm4[l][8][0], B = gm4[l][8][1];
            bf_pair(A, B, aR[0], aI[0], aR[2], aI[2]);
            bf_pair(A, B, aR[1], aI[1], aR[3], aI[3]);
        }
        // lane gates q=7..3 (lane bit 7-q)
        #pragma unroll
        for (int q = 7; q >= 3; q--)
            lane_gate(gm4[l][q][0], gm4[l][q][1], 7 - q, lane, aR, aI);

        // exchange to view B: store amps at r-major amp-addr (conflict-free)
        __syncthreads();
        #pragma unroll
        for (int r = 0; r < 4; r++) {
            sR[(r << 8) | tid] = aR[r];
            sI[(r << 8) | tid] = aI[r];
        }
        __syncthreads();
        #pragma unroll
        for (int r = 0; r < 4; r++) {
            int a = sigma((tid << 2) | r);
            int p = ADDR(a);
            aR[r] = sR[p]; aI[r] = sI[p];
        }
        // view-B gates: q=2 -> r bit0, q=1 -> r bit1, q=0 -> lane bit0
        {
            float4 A = gm4[l][2][0], B = gm4[l][2][1];
            bf_pair(A, B, aR[0], aI[0], aR[1], aI[1]);
            bf_pair(A, B, aR[2], aI[2], aR[3], aI[3]);
        }
        {
            float4 A = gm4[l][1][0], B = gm4[l][1][1];
            bf_pair(A, B, aR[0], aI[0], aR[2], aI[2]);
            bf_pair(A, B, aR[1], aI[1], aR[3], aI[3]);
        }
        lane_gate(gm4[l][0][0], gm4[l][0][1], 0, lane, aR, aI);

        // exchange back: store at view-B slot addr (conflict-free), gather with perm
        __syncthreads();
        #pragma unroll
        for (int r = 0; r < 4; r++) {
            sR[(r << 8) | tid] = aR[r];   // value of amp sigma(4*tid+r) at view-B slot addr
            sI[(r << 8) | tid] = aI[r];
        }
        __syncthreads();
        const int rng = l + 1;
        #pragma unroll
        for (int r = 0; r < 4; r++) {
            int idx = (tid << 2) | r;
            #pragma unroll
            for (int q = NQ - 1; q >= 0; q--) {
                int tgt = q + rng; if (tgt >= NQ) tgt -= NQ;
                if ((idx >> (NQ - 1 - q)) & 1) idx ^= 1 << (NQ - 1 - tgt);
            }
            int p = ADDR(sigma(idx));   // view-B slot holding amp idx
            aR[r] = sR[p]; aI[r] = sI[p];
        }
    }

    // ---- epilogue ----
    float g0Hi = 0.f, g1Hi = 0.f, g2Hi = 0.f;
    #pragma unroll
    for (int k = 0; k < 8; k++) {
        float sg = ((tid >> (7 - k)) & 1) ? -1.f : 1.f;
        g0Hi = fmaf(sg, wsh[0][k], g0Hi);
        g1Hi = fmaf(sg, wsh[1][k], g1Hi);
        g2Hi = fmaf(sg, wsh[2][k], g2Hi);
    }
    float w08 = wsh[0][8], w09 = wsh[0][9];
    float w18 = wsh[1][8], w19 = wsh[1][9];
    float w28 = wsh[2][8], w29 = wsh[2][9];
    float acc0 = 0.f, acc1 = 0.f, acc2 = 0.f;
    #pragma unroll
    for (int r = 0; r < 4; r++) {
        bool b8 = (r >> 1) & 1, b9 = r & 1;
        float pr = aR[r]*aR[r] + aI[r]*aI[r];
        acc0 = fmaf(pr, g0Hi + (b8 ? -w08 : w08) + (b9 ? -w09 : w09), acc0);
        acc1 = fmaf(pr, g1Hi + (b8 ? -w18 : w18) + (b9 ? -w19 : w19), acc1);
        acc2 = fmaf(pr, g2Hi + (b8 ? -w28 : w28) + (b9 ? -w29 : w29), acc2);
    }
    #pragma unroll
    for (int o = 16; o; o >>= 1) {
        acc0 += __shfl_xor_sync(0xffffffffu, acc0, o);
        acc1 += __shfl_xor_sync(0xffffffffu, acc1, o);
        acc2 += __shfl_xor_sync(0xffffffffu, acc2, o);
    }
    if (lane == 0) {
        wred[warp][0] = acc0; wred[warp][1] = acc1; wred[warp][2] = acc2;
    }
    __syncthreads();
    if (tid < NA) {
        float s = bproj[tid];
        #pragma unroll
        for (int w = 0; w < 8; w++) s += wred[w][tid];
        out[b * NA + tid] = s;
    }
}

extern "C" void kernel_launch(void* const* d_in, const int* in_sizes, int n_in,
                              void* d_out, int out_size) {
    const float* c_kt   = (const float*)d_in[0];
    const float* dc_kt  = (const float*)d_in[1];
    const float* vqc    = (const float*)d_in[2];
    const float* wproj  = (const float*)d_in[3];
    const float* bproj  = (const float*)d_in[4];
    const float* lalpha = (const float*)d_in[5];
    int B = in_sizes[0] / (NQ * TT);
    qh_kernel<<<B, NTH>>>(c_kt, dc_kt, vqc, wproj, bproj, lalpha, (float*)d_out);
}

// round 6
// speedup vs baseline: 3.0331x; 1.0398x over previous
#include <cuda_runtime.h>
#include <math.h>

#define NQ 10
#define DIM 1024
#define NPAIR 45
#define NG 55
#define NTASK 65
#define TT 128
#define NTH 256
#define NL 3
#define NA 3
#define PI_F 3.14159265358979323846f

// Upper-triangle (i<j) pair indices, row-major: 45 pairs.
__constant__ int c_PI[NPAIR] = {0,0,0,0,0,0,0,0,0, 1,1,1,1,1,1,1,1, 2,2,2,2,2,2,2,
                                3,3,3,3,3,3, 4,4,4,4,4, 5,5,5,5, 6,6,6, 7,7, 8};
__constant__ int c_PJ[NPAIR] = {1,2,3,4,5,6,7,8,9, 2,3,4,5,6,7,8,9, 3,4,5,6,7,8,9,
                                4,5,6,7,8,9, 5,6,7,8,9, 6,7,8,9, 7,8,9, 8,9, 9};
// Gram tasks: all (i<=j) pairs incl diagonal, row-major: 55.
__constant__ int c_TI[NG] = {0,0,0,0,0,0,0,0,0,0, 1,1,1,1,1,1,1,1,1, 2,2,2,2,2,2,2,2,
                             3,3,3,3,3,3,3, 4,4,4,4,4,4, 5,5,5,5,5, 6,6,6,6, 7,7,7, 8,8, 9};
__constant__ int c_TJ[NG] = {0,1,2,3,4,5,6,7,8,9, 1,2,3,4,5,6,7,8,9, 2,3,4,5,6,7,8,9,
                             3,4,5,6,7,8,9, 4,5,6,7,8,9, 5,6,7,8,9, 6,7,8,9, 7,8,9, 8,9, 9};
// Offset of (i,i) within the 55-list.
__constant__ int c_OFF[NQ] = {0,10,19,27,34,40,45,49,52,54};

__device__ __forceinline__ float2 cxmul(float2 a, float2 b) {
    return make_float2(a.x*b.x - a.y*b.y, a.x*b.y + a.y*b.x);
}
__device__ __forceinline__ float2 cxadd(float2 a, float2 b) {
    return make_float2(a.x + b.x, a.y + b.y);
}

// Butterfly on one amplitude pair; A=(u00,u01), B=(u10,u11) packed float4.
__device__ __forceinline__ void bf_pair(float4 A, float4 B,
                                        float& r0, float& i0, float& r1, float& i1) {
    float n0r = A.x*r0 - A.y*i0 + A.z*r1 - A.w*i1;
    float n0i = A.x*i0 + A.y*r0 + A.z*i1 + A.w*r1;
    float n1r = B.x*r0 - B.y*i0 + B.z*r1 - B.w*i1;
    float n1i = B.x*i0 + B.y*r0 + B.z*i1 + B.w*r1;
    r0 = n0r; i0 = n0i; r1 = n1r; i1 = n1i;
}

// Shuffle butterfly on lane bit k for all 4 register amps.
__device__ __forceinline__ void lane_gate(float4 A, float4 B, int k, int lane,
                                          float aR[4], float aI[4]) {
    bool bb = (lane >> k) & 1;
    float umx = bb ? B.z : A.x, umy = bb ? B.w : A.y;
    float uox = bb ? B.x : A.z, uoy = bb ? B.y : A.w;
    #pragma unroll
    for (int r = 0; r < 4; r++) {
        float pr = __shfl_xor_sync(0xffffffffu, aR[r], 1 << k);
        float pi = __shfl_xor_sync(0xffffffffu, aI[r], 1 << k);
        float nr = umx*aR[r] - umy*aI[r] + uox*pr - uoy*pi;
        float ni = umx*aI[r] + umy*aR[r] + uox*pi + uoy*pr;
        aR[r] = nr; aI[r] = ni;
    }
}

// View-B map: swap amp bits [9:7] <-> slot bits [2:0] (involution).
__device__ __forceinline__ int sigma(int j) {
    return (j & 0x078) | ((j & 7) << 7) | (j >> 7);
}
// r-major shared addressing for amplitude/slot index s.
__device__ __forceinline__ int ADDR(int s) { return ((s & 3) << 8) | (s >> 2); }
// GF(2)-linear bank swizzle (XORs strictly-higher bits into lower bits).
__device__ __forceinline__ int swz(int a) {
    return a ^ ((a >> 5) & 0xF) ^ ((a >> 1) & 8) ^ ((a >> 2) & 1);
}

__global__ __launch_bounds__(NTH, 4)
void qh_kernel(const float* __restrict__ c_kt,
               const float* __restrict__ dc_kt,
               const float* __restrict__ vqc,
               const float* __restrict__ wproj,
               const float* __restrict__ bproj,
               const float* __restrict__ lalpha,
               float* __restrict__ out)
{
    __shared__ float feat[NQ * TT];       // [k][t]
    __shared__ float2 bufA[DIM];          // exchange double-buffer A
    __shared__ float2 bufB[DIM];          // exchange double-buffer B
    __shared__ int lutA[NL][32], lutB[NL][32];  // swz(ADDR(sigma(Perm_l(.))))
    __shared__ float G[NG];
    __shared__ float Ssum[NQ];
    __shared__ float Jp[NPAIR];
    __shared__ float cth[NQ], sth[NQ], phh[NQ];
    __shared__ float thetaS[NQ], phiS[NQ];
    __shared__ float4 gm4[NL][NQ][2];
    __shared__ float wsh[NA][NQ];
    __shared__ float wred[8][4];

    const int b    = blockIdx.x;
    const int tid  = threadIdx.x;
    const int warp = tid >> 5;
    const int lane = tid & 31;

    const float* cb = c_kt  + (size_t)b * (NQ * TT);
    const float* db = dc_kt + (size_t)b * (NQ * TT);

    // ---- phase 1: stage inputs + build permutation LUTs (data-independent) ----
    for (int i = tid; i < NQ * TT; i += NTH) {
        int t = i / NQ, k = i - t * NQ;
        feat[k * TT + t] = fmaf(0.5f, db[i], cb[i]);
    }
    if (tid < NQ) {
        thetaS[tid] = cb[(TT - 1) * NQ + tid];
        phiS[tid]   = db[(TT - 1) * NQ + tid];
    }
    if (tid >= 224 && tid < 224 + NA * NQ) {
        int i = tid - 224;
        wsh[i / NQ][i - (i / NQ) * NQ] = wproj[i];
    }
    if (tid < 192) {
        int l = tid / 64, k = tid & 63;
        int idx = (k < 32) ? k : ((k - 32) << 5);
        const int rng = l + 1;
        #pragma unroll
        for (int q = NQ - 1; q >= 0; q--) {
            int tgt = q + rng; if (tgt >= NQ) tgt -= NQ;
            if ((idx >> (NQ - 1 - q)) & 1) idx ^= 1 << (NQ - 1 - tgt);
        }
        int p = swz(ADDR(sigma(idx)));
        if (k < 32) lutA[l][k] = p; else lutB[l][k - 32] = p;
    }
    __syncthreads();

    // ---- phase 2: 55 Gram dots + 10 row sums, one pass ----
    for (int tk = warp; tk < NTASK; tk += 8) {
        float s = 0.f;
        if (tk < NG) {
            const float* fi = feat + c_TI[tk] * TT;
            const float* fj = feat + c_TJ[tk] * TT;
            #pragma unroll
            for (int m = 0; m < 4; m++) {
                int t = lane + m * 32;
                s = fmaf(fi[t], fj[t], s);
            }
        } else {
            const float* fi = feat + (tk - NG) * TT;
            #pragma unroll
            for (int m = 0; m < 4; m++) s += fi[lane + m * 32];
        }
        #pragma unroll
        for (int o = 16; o; o >>= 1) s += __shfl_xor_sync(0xffffffffu, s, o);
        if (lane == 0) {
            if (tk < NG) G[tk] = s; else Ssum[tk - NG] = s;
        }
    }
    __syncthreads();

    // ---- phase 3 (parallel sub-jobs) ----
    if (tid < NPAIR) {
        int i = c_PI[tid], j = c_PJ[tid];
        float Si = Ssum[i], Sj = Ssum[j];
        const float invT = 1.f / TT, invT1 = 1.f / (TT - 1);
        float vi = (G[c_OFF[i]] - Si * Si * invT) * invT1;
        float vj = (G[c_OFF[j]] - Sj * Sj * invT) * invT1;
        float si = fmaxf(sqrtf(vi), 1e-8f);
        float sj = fmaxf(sqrtf(vj), 1e-8f);
        float num = (G[c_OFF[i] + (j - i)] - Si * Sj * invT) * invT1;
        float rho = num / (si * sj);
        Jp[tid] = __tanhf(rho * __expf(lalpha[0]));
    } else if (tid >= 64 && tid < 64 + NQ) {
        int q = tid - 64;
        float th = thetaS[q];
        cth[q] = cosf(0.5f * th);
        sth[q] = sinf(0.5f * th);
        phh[q] = 0.5f * phiS[q];
    } else if (tid >= 128 && tid < 128 + NL * NQ) {
        int idx = tid - 128;
        int l = idx / NQ, q = idx - l * NQ;
        float a  = vqc[idx * 3 + 0];
        float bb = vqc[idx * 3 + 1];
        float c  = vqc[idx * 3 + 2];
        float cb2 = cosf(0.5f * bb), sb2 = sinf(0.5f * bb);
        float apc = 0.5f * (a + c), amc = 0.5f * (a - c);
        float capc, sapc, camc, samc;
        sincosf(apc, &sapc, &capc);
        sincosf(amc, &samc, &camc);
        float2 u00 = make_float2( capc * cb2, -sapc * cb2);
        float2 u01 = make_float2(-camc * sb2, -samc * sb2);
        float2 u10 = make_float2( camc * sb2, -samc * sb2);
        float2 u11 = make_float2( capc * cb2,  sapc * cb2);
        if (l != 0) {
            // Fold preceding RY(theta/2), RZ(phi/2) into this layer's rot.
            float thq = 0.25f * thetaS[q], phq = 0.25f * phiS[q];
            float ct = cosf(thq), st = sinf(thq);
            float cp, sp; sincosf(phq, &sp, &cp);
            float2 A00 = make_float2( cp * ct, -sp * ct);
            float2 A01 = make_float2(-cp * st,  sp * st);
            float2 A10 = make_float2( cp * st,  sp * st);
            float2 A11 = make_float2( cp * ct,  sp * ct);
            float2 v00 = cxadd(cxmul(u00, A00), cxmul(u01, A10));
            float2 v01 = cxadd(cxmul(u00, A01), cxmul(u01, A11));
            float2 v10 = cxadd(cxmul(u10, A00), cxmul(u11, A10));
            float2 v11 = cxadd(cxmul(u10, A01), cxmul(u11, A11));
            u00 = v00; u01 = v01; u10 = v10; u11 = v11;
        }
        gm4[l][q][0] = make_float4(u00.x, u00.y, u01.x, u01.y);
        gm4[l][q][1] = make_float4(u10.x, u10.y, u11.x, u11.y);
    }
    __syncthreads();

    // ===================== state in registers =====================
    // slot s = (tid<<2)|r.  qubit q in 0..7 <-> tid bit (7-q); q8 <-> r bit1, q9 <-> r bit0.
    float aR[4], aI[4];
    {
        float magHi = 1.f, phHi = 0.f;
        #pragma unroll
        for (int q = 0; q < 8; q++) {
            bool t = (tid >> (7 - q)) & 1;
            magHi *= t ? sth[q] : cth[q];
            phHi  += t ? phh[q] : -phh[q];
        }
        float base = 0.f, A = 0.f, Bv = 0.f;
        int idx = 0;
        #pragma unroll
        for (int i = 0; i < 9; i++) {
            #pragma unroll
            for (int j = i + 1; j < 10; j++) {
                if (i < 8) {
                    bool ti = (tid >> (7 - i)) & 1;
                    float Jv = Jp[idx];
                    if (j < 8) {
                        bool tj = (tid >> (7 - j)) & 1;
                        base += (ti ^ tj) ? Jv : -Jv;
                    } else if (j == 8) {
                        A += ti ? Jv : -Jv;
                    } else {
                        Bv += ti ? Jv : -Jv;
                    }
                }
                idx++;
            }
        }
        float C = Jp[44];
        float c8 = cth[8], s8 = sth[8], c9 = cth[9], s9 = sth[9];
        float p8 = phh[8], p9 = phh[9];
        #pragma unroll
        for (int r = 0; r < 4; r++) {
            bool b8 = (r >> 1) & 1, b9 = r & 1;
            float mag = magHi * (b8 ? s8 : c8) * (b9 ? s9 : c9);
            float ph  = phHi + (b8 ? p8 : -p8) + (b9 ? p9 : -p9);
            float aJ  = base + (b8 ? -A : A) + (b9 ? -Bv : Bv) + ((b8 ^ b9) ? C : -C);
            ph = fmaf(0.5f * PI_F, aJ, ph);
            float sp, cp; __sincosf(ph, &sp, &cp);
            aR[r] = mag * cp; aI[r] = mag * sp;
        }
    }

    // Swizzled exchange address bases (computed once).
    const int ftid = swz(tid);  // store base: addr_r = ftid ^ cstS[r]
    int pbase;                  // gather-1 base: addr_r = fpb ^ cstG[r]
    {
        pbase = (((tid >> 5) & 3) << 8) | (tid & 0x1E) | ((tid & 1) << 7) | (tid >> 7);
    }
    const int fpb = swz(pbase);
    const int cstS[4] = {0x000, 0x108, 0x200, 0x308};   // swz(r<<8)
    const int cstG[4] = {0x00, 0x21, 0x42, 0x63};       // swz(r<<5)
    const int laIdxBase = (tid & 7) << 2;
    const int lbIdx = tid >> 3;

    #pragma unroll
    for (int l = 0; l < NL; l++) {
        // register gates q=9 (r bit0), q=8 (r bit1)
        {
            float4 A = gm4[l][9][0], B = gm4[l][9][1];
            bf_pair(A, B, aR[0], aI[0], aR[1], aI[1]);
            bf_pair(A, B, aR[2], aI[2], aR[3], aI[3]);
        }
        {
            float4 A = gm4[l][8][0], B = gm4[l][8][1];
            bf_pair(A, B, aR[0], aI[0], aR[2], aI[2]);
            bf_pair(A, B, aR[1], aI[1], aR[3], aI[3]);
        }
        // lane gates q=7..3 (lane bit 7-q)
        #pragma unroll
        for (int q = 7; q >= 3; q--)
            lane_gate(gm4[l][q][0], gm4[l][q][1], 7 - q, lane, aR, aI);

        // exchange to view B (buffer A): conflict-free store, swizzled gather
        #pragma unroll
        for (int r = 0; r < 4; r++)
            bufA[ftid ^ cstS[r]] = make_float2(aR[r], aI[r]);
        __syncthreads();
        #pragma unroll
        for (int r = 0; r < 4; r++) {
            float2 v = bufA[fpb ^ cstG[r]];
            aR[r] = v.x; aI[r] = v.y;
        }

        // view-B gates: q=2 -> r bit0, q=1 -> r bit1, q=0 -> lane bit0
        {
            float4 A = gm4[l][2][0], B = gm4[l][2][1];
            bf_pair(A, B, aR[0], aI[0], aR[1], aI[1]);
            bf_pair(A, B, aR[2], aI[2], aR[3], aI[3]);
        }
        {
            float4 A = gm4[l][1][0], B = gm4[l][1][1];
            bf_pair(A, B, aR[0], aI[0], aR[2], aI[2]);
            bf_pair(A, B, aR[1], aI[1], aR[3], aI[3]);
        }
        lane_gate(gm4[l][0][0], gm4[l][0][1], 0, lane, aR, aI);

        // exchange back + composed-CNOT permutation via linear LUT (buffer B)
        #pragma unroll
        for (int r = 0; r < 4; r++)
            bufB[ftid ^ cstS[r]] = make_float2(aR[r], aI[r]);
        __syncthreads();
        {
            int mb = lutB[l][lbIdx];
            #pragma unroll
            for (int r = 0; r < 4; r++) {
                float2 v = bufB[mb ^ lutA[l][laIdxBase | r]];
                aR[r] = v.x; aI[r] = v.y;
            }
        }
    }

    // ---- epilogue ----
    float g0Hi = 0.f, g1Hi = 0.f, g2Hi = 0.f;
    #pragma unroll
    for (int k = 0; k < 8; k++) {
        float sg = ((tid >> (7 - k)) & 1) ? -1.f : 1.f;
        g0Hi = fmaf(sg, wsh[0][k], g0Hi);
        g1Hi = fmaf(sg, wsh[1][k], g1Hi);
        g2Hi = fmaf(sg, wsh[2][k], g2Hi);
    }
    float w08 = wsh[0][8], w09 = wsh[0][9];
    float w18 = wsh[1][8], w19 = wsh[1][9];
    float w28 = wsh[2][8], w29 = wsh[2][9];
    float acc0 = 0.f, acc1 = 0.f, acc2 = 0.f;
    #pragma unroll
    for (int r = 0; r < 4; r++) {
        bool b8 = (r >> 1) & 1, b9 = r & 1;
        float pr = aR[r]*aR[r] + aI[r]*aI[r];
        acc0 = fmaf(pr, g0Hi + (b8 ? -w08 : w08) + (b9 ? -w09 : w09), acc0);
        acc1 = fmaf(pr, g1Hi + (b8 ? -w18 : w18) + (b9 ? -w19 : w19), acc1);
        acc2 = fmaf(pr, g2Hi + (b8 ? -w28 : w28) + (b9 ? -w29 : w29), acc2);
    }
    #pragma unroll
    for (int o = 16; o; o >>= 1) {
        acc0 += __shfl_xor_sync(0xffffffffu, acc0, o);
        acc1 += __shfl_xor_sync(0xffffffffu, acc1, o);
        acc2 += __shfl_xor_sync(0xffffffffu, acc2, o);
    }
    if (lane == 0) {
        wred[warp][0] = acc0; wred[warp][1] = acc1; wred[warp][2] = acc2;
    }
    __syncthreads();
    if (tid < NA) {
        float s = bproj[tid];
        #pragma unroll
        for (int w = 0; w < 8; w++) s += wred[w][tid];
        out[b * NA + tid] = s;
    }
}

extern "C" void kernel_launch(void* const* d_in, const int* in_sizes, int n_in,
                              void* d_out, int out_size) {
    const float* c_kt   = (const float*)d_in[0];
    const float* dc_kt  = (const float*)d_in[1];
    const float* vqc    = (const float*)d_in[2];
    const float* wproj  = (const float*)d_in[3];
    const float* bproj  = (const float*)d_in[4];
    const float* lalpha = (const float*)d_in[5];
    int B = in_sizes[0] / (NQ * TT);
    qh_kernel<<<B, NTH>>>(c_kt, dc_kt, vqc, wproj, bproj, lalpha, (float*)d_out);
}

// round 9
// speedup vs baseline: 3.1841x; 1.0498x over previous
#include <cuda_runtime.h>
#include <math.h>

#define NQ 10
#define DIM 1024
#define NPAIR 45
#define NG 55
#define TT 128
#define FS 133          // padded feat row stride (5k mod 32 distinct for k=0..9)
#define NTH 256
#define NL 3
#define NA 3
#define PI_F 3.14159265358979323846f

// Upper-triangle (i<j) pair indices, row-major: 45 pairs.
__constant__ int c_PI[NPAIR] = {0,0,0,0,0,0,0,0,0, 1,1,1,1,1,1,1,1, 2,2,2,2,2,2,2,
                                3,3,3,3,3,3, 4,4,4,4,4, 5,5,5,5, 6,6,6, 7,7, 8};
__constant__ int c_PJ[NPAIR] = {1,2,3,4,5,6,7,8,9, 2,3,4,5,6,7,8,9, 3,4,5,6,7,8,9,
                                4,5,6,7,8,9, 5,6,7,8,9, 6,7,8,9, 7,8,9, 8,9, 9};
// Gram tasks: all (i<=j) pairs incl diagonal, row-major: 55.
__constant__ int c_TI[NG] = {0,0,0,0,0,0,0,0,0,0, 1,1,1,1,1,1,1,1,1, 2,2,2,2,2,2,2,2,
                             3,3,3,3,3,3,3, 4,4,4,4,4,4, 5,5,5,5,5, 6,6,6,6, 7,7,7, 8,8, 9};
__constant__ int c_TJ[NG] = {0,1,2,3,4,5,6,7,8,9, 1,2,3,4,5,6,7,8,9, 2,3,4,5,6,7,8,9,
                             3,4,5,6,7,8,9, 4,5,6,7,8,9, 5,6,7,8,9, 6,7,8,9, 7,8,9, 8,9, 9};
// Offset of (i,i) within the 55-list.
__constant__ int c_OFF[NQ] = {0,10,19,27,34,40,45,49,52,54};
// Contiguous per-warp task ranges over the 55 Gram tasks.
__constant__ int c_LO[9] = {0,7,14,21,28,35,42,49,55};

__device__ __forceinline__ float2 cxmul(float2 a, float2 b) {
    return make_float2(a.x*b.x - a.y*b.y, a.x*b.y + a.y*b.x);
}
__device__ __forceinline__ float2 cxadd(float2 a, float2 b) {
    return make_float2(a.x + b.x, a.y + b.y);
}

// Butterfly on one amplitude pair; A=(u00,u01), B=(u10,u11) packed float4.
__device__ __forceinline__ void bf_pair(float4 A, float4 B,
                                        float& r0, float& i0, float& r1, float& i1) {
    float n0r = A.x*r0 - A.y*i0 + A.z*r1 - A.w*i1;
    float n0i = A.x*i0 + A.y*r0 + A.z*i1 + A.w*r1;
    float n1r = B.x*r0 - B.y*i0 + B.z*r1 - B.w*i1;
    float n1i = B.x*i0 + B.y*r0 + B.z*i1 + B.w*r1;
    r0 = n0r; i0 = n0i; r1 = n1r; i1 = n1i;
}

// Shuffle butterfly on lane bit k for all 4 register amps.
__device__ __forceinline__ void lane_gate(float4 A, float4 B, int k, int lane,
                                          float aR[4], float aI[4]) {
    bool bb = (lane >> k) & 1;
    float umx = bb ? B.z : A.x, umy = bb ? B.w : A.y;
    float uox = bb ? B.x : A.z, uoy = bb ? B.y : A.w;
    #pragma unroll
    for (int r = 0; r < 4; r++) {
        float pr = __shfl_xor_sync(0xffffffffu, aR[r], 1 << k);
        float pi = __shfl_xor_sync(0xffffffffu, aI[r], 1 << k);
        float nr = umx*aR[r] - umy*aI[r] + uox*pr - uoy*pi;
        float ni = umx*aI[r] + umy*aR[r] + uox*pi + uoy*pr;
        aR[r] = nr; aI[r] = ni;
    }
}

// View-B map: swap amp bits [9:7] <-> slot bits [2:0] (involution).
__device__ __forceinline__ int sigma(int j) {
    return (j & 0x078) | ((j & 7) << 7) | (j >> 7);
}
// r-major shared addressing for amplitude/slot index s.
__device__ __forceinline__ int ADDR(int s) { return ((s & 3) << 8) | (s >> 2); }
// GF(2)-linear bank swizzle (XORs strictly-higher bits into lower bits).
__device__ __forceinline__ int swz(int a) {
    return a ^ ((a >> 5) & 0xF) ^ ((a >> 1) & 8) ^ ((a >> 2) & 1);
}

__global__ __launch_bounds__(NTH, 4)
void qh_kernel(const float* __restrict__ c_kt,
               const float* __restrict__ dc_kt,
               const float* __restrict__ vqc,
               const float* __restrict__ wproj,
               const float* __restrict__ bproj,
               const float* __restrict__ lalpha,
               float* __restrict__ out)
{
    __shared__ float feat[NQ * FS];       // [k][t], padded stride
    __shared__ float2 bufA[DIM];          // exchange double-buffer A
    __shared__ float2 bufB[DIM];          // exchange double-buffer B
    __shared__ int lutA[NL][32], lutB[NL][32];  // swz(ADDR(sigma(Perm_l(.))))
    __shared__ float G[NG];
    __shared__ float Ssum[NQ];
    __shared__ float Jp[NPAIR];
    __shared__ float cth[NQ], sth[NQ], phh[NQ];
    __shared__ float thetaS[NQ], phiS[NQ];
    __shared__ float4 gm4[NL][NQ][2];
    __shared__ float wsh[NA][NQ];
    __shared__ float wred[8][4];

    const int b    = blockIdx.x;
    const int tid  = threadIdx.x;
    const int warp = tid >> 5;
    const int lane = tid & 31;

    const float* cb = c_kt  + (size_t)b * (NQ * TT);
    const float* db = dc_kt + (size_t)b * (NQ * TT);

    // ---- phase 1: stage inputs + build permutation LUTs (data-independent) ----
    for (int i = tid; i < NQ * TT; i += NTH) {
        int t = i / NQ, k = i - t * NQ;
        feat[k * FS + t] = fmaf(0.5f, db[i], cb[i]);   // conflict-free (stride 133)
    }
    if (tid < NQ) {
        thetaS[tid] = cb[(TT - 1) * NQ + tid];
        phiS[tid]   = db[(TT - 1) * NQ + tid];
    }
    if (tid >= 224 && tid < 224 + NA * NQ) {
        int i = tid - 224;
        wsh[i / NQ][i - (i / NQ) * NQ] = wproj[i];
    }
    if (tid < 192) {
        int l = tid / 64, k = tid & 63;
        int idx = (k < 32) ? k : ((k - 32) << 5);
        const int rng = l + 1;
        #pragma unroll
        for (int q = NQ - 1; q >= 0; q--) {
            int tgt = q + rng; if (tgt >= NQ) tgt -= NQ;
            if ((idx >> (NQ - 1 - q)) & 1) idx ^= 1 << (NQ - 1 - tgt);
        }
        int p = swz(ADDR(sigma(idx)));
        if (k < 32) lutA[l][k] = p; else lutB[l][k - 32] = p;
    }
    __syncthreads();

    // ---- phase 2: 55 Gram dots (+fused row sums), contiguous ranges, fi cached ----
    {
        const int lo = c_LO[warp], hi = c_LO[warp + 1];
        int cur_i = -1;
        float vi0=0.f, vi1=0.f, vi2=0.f, vi3=0.f;
        for (int tk = lo; tk < hi; tk++) {
            int i = c_TI[tk], j = c_TJ[tk];
            if (i != cur_i) {
                cur_i = i;
                const float* fi = feat + i * FS + lane;
                vi0 = fi[0]; vi1 = fi[32]; vi2 = fi[64]; vi3 = fi[96];
            }
            float s;
            if (j == i) {
                s = vi0*vi0 + vi1*vi1 + vi2*vi2 + vi3*vi3;
                float ss = vi0 + vi1 + vi2 + vi3;
                #pragma unroll
                for (int o = 16; o; o >>= 1) ss += __shfl_xor_sync(0xffffffffu, ss, o);
                if (lane == 0) Ssum[i] = ss;
            } else {
                const float* fj = feat + j * FS + lane;
                s = vi0*fj[0] + vi1*fj[32] + vi2*fj[64] + vi3*fj[96];
            }
            #pragma unroll
            for (int o = 16; o; o >>= 1) s += __shfl_xor_sync(0xffffffffu, s, o);
            if (lane == 0) G[tk] = s;
        }
    }
    __syncthreads();

    // ---- phase 3 (parallel sub-jobs) ----
    if (tid < NPAIR) {
        int i = c_PI[tid], j = c_PJ[tid];
        float Si = Ssum[i], Sj = Ssum[j];
        const float invT = 1.f / TT, invT1 = 1.f / (TT - 1);
        float vi = (G[c_OFF[i]] - Si * Si * invT) * invT1;
        float vj = (G[c_OFF[j]] - Sj * Sj * invT) * invT1;
        float si = fmaxf(sqrtf(vi), 1e-8f);
        float sj = fmaxf(sqrtf(vj), 1e-8f);
        float num = (G[c_OFF[i] + (j - i)] - Si * Sj * invT) * invT1;
        float rho = num / (si * sj);
        Jp[tid] = __tanhf(rho * __expf(lalpha[0]));
    } else if (tid >= 64 && tid < 64 + NQ) {
        int q = tid - 64;
        float sq, cq;
        __sincosf(0.5f * thetaS[q], &sq, &cq);
        cth[q] = cq; sth[q] = sq;
        phh[q] = 0.5f * phiS[q];
    } else if (tid >= 128 && tid < 128 + NL * NQ) {
        int idx = tid - 128;
        int l = idx / NQ, q = idx - l * NQ;
        float a  = vqc[idx * 3 + 0];
        float bb = vqc[idx * 3 + 1];
        float c  = vqc[idx * 3 + 2];
        float sb2, cb2; __sincosf(0.5f * bb, &sb2, &cb2);
        float apc = 0.5f * (a + c), amc = 0.5f * (a - c);
        float capc, sapc, camc, samc;
        __sincosf(apc, &sapc, &capc);
        __sincosf(amc, &samc, &camc);
        float2 u00 = make_float2( capc * cb2, -sapc * cb2);
        float2 u01 = make_float2(-camc * sb2, -samc * sb2);
        float2 u10 = make_float2( camc * sb2, -samc * sb2);
        float2 u11 = make_float2( capc * cb2,  sapc * cb2);
        if (l != 0) {
            // Fold preceding RY(theta/2), RZ(phi/2) into this layer's rot.
            float thq = 0.25f * thetaS[q], phq = 0.25f * phiS[q];
            float st, ct; __sincosf(thq, &st, &ct);
            float sp, cp; __sincosf(phq, &sp, &cp);
            float2 A00 = make_float2( cp * ct, -sp * ct);
            float2 A01 = make_float2(-cp * st,  sp * st);
            float2 A10 = make_float2( cp * st,  sp * st);
            float2 A11 = make_float2( cp * ct,  sp * ct);
            float2 v00 = cxadd(cxmul(u00, A00), cxmul(u01, A10));
            float2 v01 = cxadd(cxmul(u00, A01), cxmul(u01, A11));
            float2 v10 = cxadd(cxmul(u10, A00), cxmul(u11, A10));
            float2 v11 = cxadd(cxmul(u10, A01), cxmul(u11, A11));
            u00 = v00; u01 = v01; u10 = v10; u11 = v11;
        }
        gm4[l][q][0] = make_float4(u00.x, u00.y, u01.x, u01.y);
        gm4[l][q][1] = make_float4(u10.x, u10.y, u11.x, u11.y);
    }
    __syncthreads();

    // ===================== state in registers =====================
    // slot s = (tid<<2)|r.  qubit q in 0..7 <-> tid bit (7-q); q8 <-> r bit1, q9 <-> r bit0.
    float aR[4], aI[4];
    {
        float magHi = 1.f, phHi = 0.f;
        #pragma unroll
        for (int q = 0; q < 8; q++) {
            bool t = (tid >> (7 - q)) & 1;
            magHi *= t ? sth[q] : cth[q];
            phHi  += t ? phh[q] : -phh[q];
        }
        float base = 0.f, A = 0.f, Bv = 0.f;
        int idx = 0;
        #pragma unroll
        for (int i = 0; i < 9; i++) {
            #pragma unroll
            for (int j = i + 1; j < 10; j++) {
                if (i < 8) {
                    bool ti = (tid >> (7 - i)) & 1;
                    float Jv = Jp[idx];
                    if (j < 8) {
                        bool tj = (tid >> (7 - j)) & 1;
                        base += (ti ^ tj) ? Jv : -Jv;
                    } else if (j == 8) {
                        A += ti ? Jv : -Jv;
                    } else {
                        Bv += ti ? Jv : -Jv;
                    }
                }
                idx++;
            }
        }
        float C = Jp[44];
        float c8 = cth[8], s8 = sth[8], c9 = cth[9], s9 = sth[9];
        float p8 = phh[8], p9 = phh[9];
        #pragma unroll
        for (int r = 0; r < 4; r++) {
            bool b8 = (r >> 1) & 1, b9 = r & 1;
            float mag = magHi * (b8 ? s8 : c8) * (b9 ? s9 : c9);
            float ph  = phHi + (b8 ? p8 : -p8) + (b9 ? p9 : -p9);
            float aJ  = base + (b8 ? -A : A) + (b9 ? -Bv : Bv) + ((b8 ^ b9) ? C : -C);
            ph = fmaf(0.5f * PI_F, aJ, ph);
            float sp, cp; __sincosf(ph, &sp, &cp);
            aR[r] = mag * cp; aI[r] = mag * sp;
        }
    }

    // Swizzled exchange address bases (computed once).
    const int ftid = swz(tid);  // store base: addr_r = ftid ^ cstS[r]
    int pbase;                  // gather-1 base: addr_r = fpb ^ cstG[r]
    {
        pbase = (((tid >> 5) & 3) << 8) | (tid & 0x1E) | ((tid & 1) << 7) | (tid >> 7);
    }
    const int fpb = swz(pbase);
    const int cstS[4] = {0x000, 0x108, 0x200, 0x308};   // swz(r<<8)
    const int cstG[4] = {0x00, 0x21, 0x42, 0x63};       // swz(r<<5)
    const int laIdxBase = (tid & 7) << 2;
    const int lbIdx = tid >> 3;

    #pragma unroll
    for (int l = 0; l < NL; l++) {
        // register gates q=9 (r bit0), q=8 (r bit1)
        {
            float4 A = gm4[l][9][0], B = gm4[l][9][1];
            bf_pair(A, B, aR[0], aI[0], aR[1], aI[1]);
            bf_pair(A, B, aR[2], aI[2], aR[3], aI[3]);
        }
        {
            float4 A = gm4[l][8][0], B = gm4[l][8][1];
            bf_pair(A, B, aR[0], aI[0], aR[2], aI[2]);
            bf_pair(A, B, aR[1], aI[1], aR[3], aI[3]);
        }
        // lane gates q=7..3 (lane bit 7-q)
        #pragma unroll
        for (int q = 7; q >= 3; q--)
            lane_gate(gm4[l][q][0], gm4[l][q][1], 7 - q, lane, aR, aI);

        // exchange to view B (buffer A): conflict-free store, swizzled gather
        #pragma unroll
        for (int r = 0; r < 4; r++)
            bufA[ftid ^ cstS[r]] = make_float2(aR[r], aI[r]);
        __syncthreads();
        #pragma unroll
        for (int r = 0; r < 4; r++) {
            float2 v = bufA[fpb ^ cstG[r]];
            aR[r] = v.x; aI[r] = v.y;
        }

        // view-B gates: q=2 -> r bit0, q=1 -> r bit1, q=0 -> lane bit0
        {
            float4 A = gm4[l][2][0], B = gm4[l][2][1];
            bf_pair(A, B, aR[0], aI[0], aR[1], aI[1]);
            bf_pair(A, B, aR[2], aI[2], aR[3], aI[3]);
        }
        {
            float4 A = gm4[l][1][0], B = gm4[l][1][1];
            bf_pair(A, B, aR[0], aI[0], aR[2], aI[2]);
            bf_pair(A, B, aR[1], aI[1], aR[3], aI[3]);
        }
        lane_gate(gm4[l][0][0], gm4[l][0][1], 0, lane, aR, aI);

        // exchange back + composed-CNOT permutation via linear LUT (buffer B)
        #pragma unroll
        for (int r = 0; r < 4; r++)
            bufB[ftid ^ cstS[r]] = make_float2(aR[r], aI[r]);
        __syncthreads();
        {
            int mb = lutB[l][lbIdx];
            #pragma unroll
            for (int r = 0; r < 4; r++) {
                float2 v = bufB[mb ^ lutA[l][laIdxBase | r]];
                aR[r] = v.x; aI[r] = v.y;
            }
        }
    }

    // ---- epilogue ----
    float g0Hi = 0.f, g1Hi = 0.f, g2Hi = 0.f;
    #pragma unroll
    for (int k = 0; k < 8; k++) {
        float sg = ((tid >> (7 - k)) & 1) ? -1.f : 1.f;
        g0Hi = fmaf(sg, wsh[0][k], g0Hi);
        g1Hi = fmaf(sg, wsh[1][k], g1Hi);
        g2Hi = fmaf(sg, wsh[2][k], g2Hi);
    }
    float w08 = wsh[0][8], w09 = wsh[0][9];
    float w18 = wsh[1][8], w19 = wsh[1][9];
    float w28 = wsh[2][8], w29 = wsh[2][9];
    float acc0 = 0.f, acc1 = 0.f, acc2 = 0.f;
    #pragma unroll
    for (int r = 0; r < 4; r++) {
        bool b8 = (r >> 1) & 1, b9 = r & 1;
        float pr = aR[r]*aR[r] + aI[r]*aI[r];
        acc0 = fmaf(pr, g0Hi + (b8 ? -w08 : w08) + (b9 ? -w09 : w09), acc0);
        acc1 = fmaf(pr, g1Hi + (b8 ? -w18 : w18) + (b9 ? -w19 : w19), acc1);
        acc2 = fmaf(pr, g2Hi + (b8 ? -w28 : w28) + (b9 ? -w29 : w29), acc2);
    }
    #pragma unroll
    for (int o = 16; o; o >>= 1) {
        acc0 += __shfl_xor_sync(0xffffffffu, acc0, o);
        acc1 += __shfl_xor_sync(0xffffffffu, acc1, o);
        acc2 += __shfl_xor_sync(0xffffffffu, acc2, o);
    }
    if (lane == 0) {
        wred[warp][0] = acc0; wred[warp][1] = acc1; wred[warp][2] = acc2;
    }
    __syncthreads();
    if (tid < NA) {
        float s = bproj[tid];
        #pragma unroll
        for (int w = 0; w < 8; w++) s += wred[w][tid];
        out[b * NA + tid] = s;
    }
}

extern "C" void kernel_launch(void* const* d_in, const int* in_sizes, int n_in,
                              void* d_out, int out_size) {
    const float* c_kt   = (const float*)d_in[0];
    const float* dc_kt  = (const float*)d_in[1];
    const float* vqc    = (const float*)d_in[2];
    const float* wproj  = (const float*)d_in[3];
    const float* bproj  = (const float*)d_in[4];
    const float* lalpha = (const float*)d_in[5];
    int B = in_sizes[0] / (NQ * TT);
    qh_kernel<<<B, NTH>>>(c_kt, dc_kt, vqc, wproj, bproj, lalpha, (float*)d_out);
}

// round 10
// speedup vs baseline: 3.3842x; 1.0629x over previous
#include <cuda_runtime.h>
#include <math.h>

#define NQ 10
#define DIM 1024
#define NPAIR 45
#define NG 55
#define TT 128
#define FS 133          // padded feat row stride (5k mod 32 distinct for k=0..9)
#define NTH 256
#define NL 3
#define NA 3
#define PI_F 3.14159265358979323846f

// Upper-triangle (i<j) pair indices, row-major: 45 pairs.
__constant__ int c_PI[NPAIR] = {0,0,0,0,0,0,0,0,0, 1,1,1,1,1,1,1,1, 2,2,2,2,2,2,2,
                                3,3,3,3,3,3, 4,4,4,4,4, 5,5,5,5, 6,6,6, 7,7, 8};
__constant__ int c_PJ[NPAIR] = {1,2,3,4,5,6,7,8,9, 2,3,4,5,6,7,8,9, 3,4,5,6,7,8,9,
                                4,5,6,7,8,9, 5,6,7,8,9, 6,7,8,9, 7,8,9, 8,9, 9};
// Gram tasks: all (i<=j) pairs incl diagonal, row-major: 55.
__constant__ int c_TI[NG] = {0,0,0,0,0,0,0,0,0,0, 1,1,1,1,1,1,1,1,1, 2,2,2,2,2,2,2,2,
                             3,3,3,3,3,3,3, 4,4,4,4,4,4, 5,5,5,5,5, 6,6,6,6, 7,7,7, 8,8, 9};
__constant__ int c_TJ[NG] = {0,1,2,3,4,5,6,7,8,9, 1,2,3,4,5,6,7,8,9, 2,3,4,5,6,7,8,9,
                             3,4,5,6,7,8,9, 4,5,6,7,8,9, 5,6,7,8,9, 6,7,8,9, 7,8,9, 8,9, 9};
// Offset of (i,i) within the 55-list.
__constant__ int c_OFF[NQ] = {0,10,19,27,34,40,45,49,52,54};
// Contiguous per-warp task ranges over the 55 Gram tasks.
__constant__ int c_LO[9] = {0,7,14,21,28,35,42,49,55};

__device__ __forceinline__ int idx45(int i, int j) {   // Jp index for pair (i<j)
    return i * 9 - ((i * (i + 1)) >> 1) + j - 1;
}

__device__ __forceinline__ float2 cxmul(float2 a, float2 b) {
    return make_float2(a.x*b.x - a.y*b.y, a.x*b.y + a.y*b.x);
}
__device__ __forceinline__ float2 cxadd(float2 a, float2 b) {
    return make_float2(a.x + b.x, a.y + b.y);
}

// Butterfly on one amplitude pair; A=(u00,u01), B=(u10,u11) packed float4.
__device__ __forceinline__ void bf_pair(float4 A, float4 B,
                                        float& r0, float& i0, float& r1, float& i1) {
    float n0r = A.x*r0 - A.y*i0 + A.z*r1 - A.w*i1;
    float n0i = A.x*i0 + A.y*r0 + A.z*i1 + A.w*r1;
    float n1r = B.x*r0 - B.y*i0 + B.z*r1 - B.w*i1;
    float n1i = B.x*i0 + B.y*r0 + B.z*i1 + B.w*r1;
    r0 = n0r; i0 = n0i; r1 = n1r; i1 = n1i;
}

// Shuffle butterfly on lane bit k for all 4 register amps.
__device__ __forceinline__ void lane_gate(float4 A, float4 B, int k, int lane,
                                          float aR[4], float aI[4]) {
    bool bb = (lane >> k) & 1;
    float umx = bb ? B.z : A.x, umy = bb ? B.w : A.y;
    float uox = bb ? B.x : A.z, uoy = bb ? B.y : A.w;
    #pragma unroll
    for (int r = 0; r < 4; r++) {
        float pr = __shfl_xor_sync(0xffffffffu, aR[r], 1 << k);
        float pi = __shfl_xor_sync(0xffffffffu, aI[r], 1 << k);
        float nr = umx*aR[r] - umy*aI[r] + uox*pr - uoy*pi;
        float ni = umx*aI[r] + umy*aR[r] + uox*pi + uoy*pr;
        aR[r] = nr; aI[r] = ni;
    }
}

// View-B map: swap amp bits [9:7] <-> slot bits [2:0] (involution).
__device__ __forceinline__ int sigma(int j) {
    return (j & 0x078) | ((j & 7) << 7) | (j >> 7);
}
// r-major shared addressing for amplitude/slot index s.
__device__ __forceinline__ int ADDR(int s) { return ((s & 3) << 8) | (s >> 2); }
// GF(2)-linear bank swizzle (XORs strictly-higher bits into lower bits).
__device__ __forceinline__ int swz(int a) {
    return a ^ ((a >> 5) & 0xF) ^ ((a >> 1) & 8) ^ ((a >> 2) & 1);
}

__global__ __launch_bounds__(NTH, 4)
void qh_kernel(const float* __restrict__ c_kt,
               const float* __restrict__ dc_kt,
               const float* __restrict__ vqc,
               const float* __restrict__ wproj,
               const float* __restrict__ bproj,
               const float* __restrict__ lalpha,
               float* __restrict__ out)
{
    __shared__ float feat[NQ * FS];       // [k][t], padded stride
    __shared__ float2 bufA[DIM];          // exchange double-buffer A
    __shared__ float2 bufB[DIM];          // exchange double-buffer B
    __shared__ int lutA[NL][32], lutB[NL][32];  // swz(ADDR(sigma(Perm_l(.))))
    __shared__ float G[NG];
    __shared__ float Ssum[NQ];
    __shared__ float Jp[NPAIR];
    __shared__ float cth[NQ], sth[NQ], phh[NQ];
    __shared__ float thetaS[NQ], phiS[NQ];
    __shared__ float4 gm4[NL][NQ][2];
    __shared__ float wsh[NA][NQ];
    __shared__ float wred[8][4];
    // nibble tables: h1 = tid[7:4] (qubits 0-3), h2 = tid[3:0] (qubits 4-7)
    __shared__ float T1mag[16], T1ph[16], T1J[16], TA1[16], TB1[16];
    __shared__ float T2mag[16], T2ph[16], T2J[16], TA2[16], TB2[16];
    __shared__ float Rrow[4][16];          // cross-nibble J row sums
    __shared__ float W1[NA][16], W2[NA][16];  // epilogue +/- w sums

    const int b    = blockIdx.x;
    const int tid  = threadIdx.x;
    const int warp = tid >> 5;
    const int lane = tid & 31;

    const float* cb = c_kt  + (size_t)b * (NQ * TT);
    const float* db = dc_kt + (size_t)b * (NQ * TT);

    // ---- phase 1: stage inputs + build permutation LUTs (data-independent) ----
    for (int i = tid; i < NQ * TT; i += NTH) {
        int t = i / NQ, k = i - t * NQ;
        feat[k * FS + t] = fmaf(0.5f, db[i], cb[i]);   // conflict-free (stride 133)
    }
    if (tid < NQ) {
        thetaS[tid] = cb[(TT - 1) * NQ + tid];
        phiS[tid]   = db[(TT - 1) * NQ + tid];
    }
    if (tid >= 224 && tid < 224 + NA * NQ) {
        int i = tid - 224;
        wsh[i / NQ][i - (i / NQ) * NQ] = wproj[i];
    }
    if (tid < 192) {
        int l = tid / 64, k = tid & 63;
        int idx = (k < 32) ? k : ((k - 32) << 5);
        const int rng = l + 1;
        #pragma unroll
        for (int q = NQ - 1; q >= 0; q--) {
            int tgt = q + rng; if (tgt >= NQ) tgt -= NQ;
            if ((idx >> (NQ - 1 - q)) & 1) idx ^= 1 << (NQ - 1 - tgt);
        }
        int p = swz(ADDR(sigma(idx)));
        if (k < 32) lutA[l][k] = p; else lutB[l][k - 32] = p;
    }
    __syncthreads();

    // ---- phase 2: 55 Gram dots (+fused row sums), contiguous ranges, fi cached ----
    {
        const int lo = c_LO[warp], hi = c_LO[warp + 1];
        int cur_i = -1;
        float vi0=0.f, vi1=0.f, vi2=0.f, vi3=0.f;
        for (int tk = lo; tk < hi; tk++) {
            int i = c_TI[tk], j = c_TJ[tk];
            if (i != cur_i) {
                cur_i = i;
                const float* fi = feat + i * FS + lane;
                vi0 = fi[0]; vi1 = fi[32]; vi2 = fi[64]; vi3 = fi[96];
            }
            float s;
            if (j == i) {
                s = vi0*vi0 + vi1*vi1 + vi2*vi2 + vi3*vi3;
                float ss = vi0 + vi1 + vi2 + vi3;
                #pragma unroll
                for (int o = 16; o; o >>= 1) ss += __shfl_xor_sync(0xffffffffu, ss, o);
                if (lane == 0) Ssum[i] = ss;
            } else {
                const float* fj = feat + j * FS + lane;
                s = vi0*fj[0] + vi1*fj[32] + vi2*fj[64] + vi3*fj[96];
            }
            #pragma unroll
            for (int o = 16; o; o >>= 1) s += __shfl_xor_sync(0xffffffffu, s, o);
            if (lane == 0) G[tk] = s;
        }
    }
    __syncthreads();

    // ---- phase 3 (parallel sub-jobs) ----
    if (tid < NPAIR) {
        int i = c_PI[tid], j = c_PJ[tid];
        float Si = Ssum[i], Sj = Ssum[j];
        const float invT = 1.f / TT, invT1 = 1.f / (TT - 1);
        float vi = (G[c_OFF[i]] - Si * Si * invT) * invT1;
        float vj = (G[c_OFF[j]] - Sj * Sj * invT) * invT1;
        float si = fmaxf(sqrtf(vi), 1e-8f);
        float sj = fmaxf(sqrtf(vj), 1e-8f);
        float num = (G[c_OFF[i] + (j - i)] - Si * Sj * invT) * invT1;
        float rho = num / (si * sj);
        Jp[tid] = __tanhf(rho * __expf(lalpha[0]));
    } else if (tid >= 64 && tid < 64 + NQ) {
        int q = tid - 64;
        float sq, cq;
        __sincosf(0.5f * thetaS[q], &sq, &cq);
        cth[q] = cq; sth[q] = sq;
        phh[q] = 0.5f * phiS[q];
    } else if (tid >= 128 && tid < 128 + NL * NQ) {
        int idx = tid - 128;
        int l = idx / NQ, q = idx - l * NQ;
        float a  = vqc[idx * 3 + 0];
        float bb = vqc[idx * 3 + 1];
        float c  = vqc[idx * 3 + 2];
        float sb2, cb2; __sincosf(0.5f * bb, &sb2, &cb2);
        float apc = 0.5f * (a + c), amc = 0.5f * (a - c);
        float capc, sapc, camc, samc;
        __sincosf(apc, &sapc, &capc);
        __sincosf(amc, &samc, &camc);
        float2 u00 = make_float2( capc * cb2, -sapc * cb2);
        float2 u01 = make_float2(-camc * sb2, -samc * sb2);
        float2 u10 = make_float2( camc * sb2, -samc * sb2);
        float2 u11 = make_float2( capc * cb2,  sapc * cb2);
        if (l != 0) {
            // Fold preceding RY(theta/2), RZ(phi/2) into this layer's rot.
            float thq = 0.25f * thetaS[q], phq = 0.25f * phiS[q];
            float st, ct; __sincosf(thq, &st, &ct);
            float sp, cp; __sincosf(phq, &sp, &cp);
            float2 A00 = make_float2( cp * ct, -sp * ct);
            float2 A01 = make_float2(-cp * st,  sp * st);
            float2 A10 = make_float2( cp * st,  sp * st);
            float2 A11 = make_float2( cp * ct,  sp * ct);
            float2 v00 = cxadd(cxmul(u00, A00), cxmul(u01, A10));
            float2 v01 = cxadd(cxmul(u00, A01), cxmul(u01, A11));
            float2 v10 = cxadd(cxmul(u10, A00), cxmul(u11, A10));
            float2 v11 = cxadd(cxmul(u10, A01), cxmul(u11, A11));
            u00 = v00; u01 = v01; u10 = v10; u11 = v11;
        }
        gm4[l][q][0] = make_float4(u00.x, u00.y, u01.x, u01.y);
        gm4[l][q][1] = make_float4(u10.x, u10.y, u11.x, u11.y);
    }
    __syncthreads();

    // ---- phase 3.5: build nibble tables (needs Jp, cth/sth/phh, wsh) ----
    if (tid < 16) {
        // qubits 0..3; bit of q = (h >> (3-q)) & 1
        int h = tid;
        float m = 1.f, p = 0.f, jj = 0.f, aa = 0.f, bv = 0.f;
        #pragma unroll
        for (int q = 0; q < 4; q++) {
            bool bit = (h >> (3 - q)) & 1;
            m *= bit ? sth[q] : cth[q];
            p += bit ? phh[q] : -phh[q];
            float ja = Jp[idx45(q, 8)], jb = Jp[idx45(q, 9)];
            aa += bit ? ja : -ja;
            bv += bit ? jb : -jb;
        }
        #pragma unroll
        for (int i = 0; i < 3; i++)
            #pragma unroll
            for (int j2 = i + 1; j2 < 4; j2++) {
                bool si = (h >> (3 - i)) & 1, sj = (h >> (3 - j2)) & 1;
                float v = Jp[idx45(i, j2)];
                jj += (si ^ sj) ? v : -v;
            }
        T1mag[h] = m; T1ph[h] = p; T1J[h] = jj; TA1[h] = aa; TB1[h] = bv;
    } else if (tid < 32) {
        // qubits 4..7; bit of q = (h >> (7-q)) & 1
        int h = tid - 16;
        float m = 1.f, p = 0.f, jj = 0.f, aa = 0.f, bv = 0.f;
        #pragma unroll
        for (int q = 4; q < 8; q++) {
            bool bit = (h >> (7 - q)) & 1;
            m *= bit ? sth[q] : cth[q];
            p += bit ? phh[q] : -phh[q];
            float ja = Jp[idx45(q, 8)], jb = Jp[idx45(q, 9)];
            aa += bit ? ja : -ja;
            bv += bit ? jb : -jb;
        }
        #pragma unroll
        for (int i = 4; i < 7; i++)
            #pragma unroll
            for (int j2 = i + 1; j2 < 8; j2++) {
                bool si = (h >> (7 - i)) & 1, sj = (h >> (7 - j2)) & 1;
                float v = Jp[idx45(i, j2)];
                jj += (si ^ sj) ? v : -v;
            }
        T2mag[h] = m; T2ph[h] = p; T2J[h] = jj; TA2[h] = aa; TB2[h] = bv;
    } else if (tid < 96) {
        // cross-nibble rows: Rrow[i][h2] = sum_j (bit_j ? +J_ij : -J_ij), i in 0..3, j in 4..7
        int e = tid - 32;
        int i = e >> 4, h2 = e & 15;
        float r = 0.f;
        #pragma unroll
        for (int j2 = 4; j2 < 8; j2++) {
            bool bit = (h2 >> (7 - j2)) & 1;
            float v = Jp[idx45(i, j2)];
            r += bit ? v : -v;
        }
        Rrow[i][h2] = r;
    } else if (tid < 192) {
        // epilogue sign-weight tables
        int e = tid - 96;           // 0..95
        int half = e / 48;          // 0 -> W1 (k=0..3), 1 -> W2 (k=4..7)
        int rem = e - half * 48;
        int a = rem >> 4, h = rem & 15;
        float g = 0.f;
        #pragma unroll
        for (int k = 0; k < 4; k++) {
            int q = half * 4 + k;
            bool bit = (h >> (3 - k)) & 1;   // h bit layout matches (h1 for half 0, h2 for half 1)
            float w = wsh[a][q];
            g += bit ? -w : w;
        }
        if (half == 0) W1[a][h] = g; else W2[a][h] = g;
    }
    __syncthreads();

    // ===================== state in registers =====================
    // slot s = (tid<<2)|r.  qubit q in 0..7 <-> tid bit (7-q); q8 <-> r bit1, q9 <-> r bit0.
    const int h1 = tid >> 4, h2 = tid & 15;
    float aR[4], aI[4];
    {
        float magHi = T1mag[h1] * T2mag[h2];
        float phHi  = T1ph[h1] + T2ph[h2];
        float base  = T1J[h1] + T2J[h2];
        #pragma unroll
        for (int i = 0; i < 4; i++) {
            bool ti = (h1 >> (3 - i)) & 1;
            float rv = Rrow[i][h2];
            base += ti ? -rv : rv;
        }
        float A  = TA1[h1] + TA2[h2];
        float Bv = TB1[h1] + TB2[h2];
        float C = Jp[44];
        float c8 = cth[8], s8 = sth[8], c9 = cth[9], s9 = sth[9];
        float p8 = phh[8], p9 = phh[9];
        #pragma unroll
        for (int r = 0; r < 4; r++) {
            bool b8 = (r >> 1) & 1, b9 = r & 1;
            float mag = magHi * (b8 ? s8 : c8) * (b9 ? s9 : c9);
            float ph  = phHi + (b8 ? p8 : -p8) + (b9 ? p9 : -p9);
            float aJ  = base + (b8 ? -A : A) + (b9 ? -Bv : Bv) + ((b8 ^ b9) ? C : -C);
            ph = fmaf(0.5f * PI_F, aJ, ph);
            float sp, cp; __sincosf(ph, &sp, &cp);
            aR[r] = mag * cp; aI[r] = mag * sp;
        }
    }

    // Swizzled exchange address bases (computed once).
    const int ftid = swz(tid);  // store base: addr_r = ftid ^ cstS[r]
    int pbase;                  // gather-1 base: addr_r = fpb ^ cstG[r]
    {
        pbase = (((tid >> 5) & 3) << 8) | (tid & 0x1E) | ((tid & 1) << 7) | (tid >> 7);
    }
    const int fpb = swz(pbase);
    const int cstS[4] = {0x000, 0x108, 0x200, 0x308};   // swz(r<<8)
    const int cstG[4] = {0x00, 0x21, 0x42, 0x63};       // swz(r<<5)
    const int laIdxBase = (tid & 7) << 2;
    const int lbIdx = tid >> 3;

    #pragma unroll
    for (int l = 0; l < NL; l++) {
        // register gates q=9 (r bit0), q=8 (r bit1)
        {
            float4 A = gm4[l][9][0], B = gm4[l][9][1];
            bf_pair(A, B, aR[0], aI[0], aR[1], aI[1]);
            bf_pair(A, B, aR[2], aI[2], aR[3], aI[3]);
        }
        {
            float4 A = gm4[l][8][0], B = gm4[l][8][1];
            bf_pair(A, B, aR[0], aI[0], aR[2], aI[2]);
            bf_pair(A, B, aR[1], aI[1], aR[3], aI[3]);
        }
        // lane gates q=7..3 (lane bit 7-q)
        #pragma unroll
        for (int q = 7; q >= 3; q--)
            lane_gate(gm4[l][q][0], gm4[l][q][1], 7 - q, lane, aR, aI);

        // exchange to view B (buffer A): conflict-free store, swizzled gather
        #pragma unroll
        for (int r = 0; r < 4; r++)
            bufA[ftid ^ cstS[r]] = make_float2(aR[r], aI[r]);
        __syncthreads();
        #pragma unroll
        for (int r = 0; r < 4; r++) {
            float2 v = bufA[fpb ^ cstG[r]];
            aR[r] = v.x; aI[r] = v.y;
        }

        // view-B gates: q=2 -> r bit0, q=1 -> r bit1, q=0 -> lane bit0
        {
            float4 A = gm4[l][2][0], B = gm4[l][2][1];
            bf_pair(A, B, aR[0], aI[0], aR[1], aI[1]);
            bf_pair(A, B, aR[2], aI[2], aR[3], aI[3]);
        }
        {
            float4 A = gm4[l][1][0], B = gm4[l][1][1];
            bf_pair(A, B, aR[0], aI[0], aR[2], aI[2]);
            bf_pair(A, B, aR[1], aI[1], aR[3], aI[3]);
        }
        lane_gate(gm4[l][0][0], gm4[l][0][1], 0, lane, aR, aI);

        // exchange back + composed-CNOT permutation via linear LUT (buffer B)
        #pragma unroll
        for (int r = 0; r < 4; r++)
            bufB[ftid ^ cstS[r]] = make_float2(aR[r], aI[r]);
        __syncthreads();
        {
            int mb = lutB[l][lbIdx];
            #pragma unroll
            for (int r = 0; r < 4; r++) {
                float2 v = bufB[mb ^ lutA[l][laIdxBase | r]];
                aR[r] = v.x; aI[r] = v.y;
            }
        }
    }

    // ---- epilogue (table-based sign weights) ----
    float g0Hi = W1[0][h1] + W2[0][h2];
    float g1Hi = W1[1][h1] + W2[1][h2];
    float g2Hi = W1[2][h1] + W2[2][h2];
    float w08 = wsh[0][8], w09 = wsh[0][9];
    float w18 = wsh[1][8], w19 = wsh[1][9];
    float w28 = wsh[2][8], w29 = wsh[2][9];
    float acc0 = 0.f, acc1 = 0.f, acc2 = 0.f;
    #pragma unroll
    for (int r = 0; r < 4; r++) {
        bool b8 = (r >> 1) & 1, b9 = r & 1;
        float pr = aR[r]*aR[r] + aI[r]*aI[r];
        acc0 = fmaf(pr, g0Hi + (b8 ? -w08 : w08) + (b9 ? -w09 : w09), acc0);
        acc1 = fmaf(pr, g1Hi + (b8 ? -w18 : w18) + (b9 ? -w19 : w19), acc1);
        acc2 = fmaf(pr, g2Hi + (b8 ? -w28 : w28) + (b9 ? -w29 : w29), acc2);
    }
    #pragma unroll
    for (int o = 16; o; o >>= 1) {
        acc0 += __shfl_xor_sync(0xffffffffu, acc0, o);
        acc1 += __shfl_xor_sync(0xffffffffu, acc1, o);
        acc2 += __shfl_xor_sync(0xffffffffu, acc2, o);
    }
    if (lane == 0) {
        wred[warp][0] = acc0; wred[warp][1] = acc1; wred[warp][2] = acc2;
    }
    __syncthreads();
    if (tid < NA) {
        float s = bproj[tid];
        #pragma unroll
        for (int w = 0; w < 8; w++) s += wred[w][tid];
        out[b * NA + tid] = s;
    }
}

extern "C" void kernel_launch(void* const* d_in, const int* in_sizes, int n_in,
                              void* d_out, int out_size) {
    const float* c_kt   = (const float*)d_in[0];
    const float* dc_kt  = (const float*)d_in[1];
    const float* vqc    = (const float*)d_in[2];
    const float* wproj  = (const float*)d_in[3];
    const float* bproj  = (const float*)d_in[4];
    const float* lalpha = (const float*)d_in[5];
    int B = in_sizes[0] / (NQ * TT);
    qh_kernel<<<B, NTH>>>(c_kt, dc_kt, vqc, wproj, bproj, lalpha, (float*)d_out);
}

// round 12
// speedup vs baseline: 3.7382x; 1.1046x over previous
#include <cuda_runtime.h>
#include <math.h>

#define NQ 10
#define DIM 1024
#define NPAIR 45
#define NG 55
#define TT 128
#define FS 133          // padded feat row stride (5k mod 32 distinct for k=0..9)
#define NTH 256
#define NL 3
#define NA 3
#define PI_F 3.14159265358979323846f

// Upper-triangle (i<j) pair indices, row-major: 45 pairs.
__constant__ int c_PI[NPAIR] = {0,0,0,0,0,0,0,0,0, 1,1,1,1,1,1,1,1, 2,2,2,2,2,2,2,
                                3,3,3,3,3,3, 4,4,4,4,4, 5,5,5,5, 6,6,6, 7,7, 8};
__constant__ int c_PJ[NPAIR] = {1,2,3,4,5,6,7,8,9, 2,3,4,5,6,7,8,9, 3,4,5,6,7,8,9,
                                4,5,6,7,8,9, 5,6,7,8,9, 6,7,8,9, 7,8,9, 8,9, 9};
// Gram tasks: all (i<=j) pairs incl diagonal, row-major: 55.
__constant__ int c_TI[NG] = {0,0,0,0,0,0,0,0,0,0, 1,1,1,1,1,1,1,1,1, 2,2,2,2,2,2,2,2,
                             3,3,3,3,3,3,3, 4,4,4,4,4,4, 5,5,5,5,5, 6,6,6,6, 7,7,7, 8,8, 9};
__constant__ int c_TJ[NG] = {0,1,2,3,4,5,6,7,8,9, 1,2,3,4,5,6,7,8,9, 2,3,4,5,6,7,8,9,
                             3,4,5,6,7,8,9, 4,5,6,7,8,9, 5,6,7,8,9, 6,7,8,9, 7,8,9, 8,9, 9};
// Offset of (i,i) within the 55-list.
__constant__ int c_OFF[NQ] = {0,10,19,27,34,40,45,49,52,54};
// Contiguous per-warp task ranges over the 55 Gram tasks.
__constant__ int c_LO[9] = {0,7,14,21,28,35,42,49,55};

__device__ __forceinline__ int idx45(int i, int j) {   // Jp index for pair (i<j)
    return i * 9 - ((i * (i + 1)) >> 1) + j - 1;
}

__device__ __forceinline__ float2 cxmul(float2 a, float2 b) {
    return make_float2(a.x*b.x - a.y*b.y, a.x*b.y + a.y*b.x);
}
__device__ __forceinline__ float2 cxadd(float2 a, float2 b) {
    return make_float2(a.x + b.x, a.y + b.y);
}

// Butterfly on one amplitude pair; A=(u00,u01), B=(u10,u11) packed float4.
__device__ __forceinline__ void bf_pair(float4 A, float4 B,
                                        float& r0, float& i0, float& r1, float& i1) {
    float n0r = A.x*r0 - A.y*i0 + A.z*r1 - A.w*i1;
    float n0i = A.x*i0 + A.y*r0 + A.z*i1 + A.w*r1;
    float n1r = B.x*r0 - B.y*i0 + B.z*r1 - B.w*i1;
    float n1i = B.x*i0 + B.y*r0 + B.z*i1 + B.w*r1;
    r0 = n0r; i0 = n0i; r1 = n1r; i1 = n1i;
}

// Shuffle butterfly on lane bit k; U=(um.x,um.y,uo.x,uo.y) already bit-selected.
__device__ __forceinline__ void lane_gate(float4 U, int k,
                                          float aR[4], float aI[4]) {
    #pragma unroll
    for (int r = 0; r < 4; r++) {
        float pr = __shfl_xor_sync(0xffffffffu, aR[r], 1 << k);
        float pi = __shfl_xor_sync(0xffffffffu, aI[r], 1 << k);
        float nr = U.x*aR[r] - U.y*aI[r] + U.z*pr - U.w*pi;
        float ni = U.x*aI[r] + U.y*aR[r] + U.z*pi + U.w*pr;
        aR[r] = nr; aI[r] = ni;
    }
}

// View-B map: swap amp bits [9:7] <-> slot bits [2:0] (involution).
__device__ __forceinline__ int sigma(int j) {
    return (j & 0x078) | ((j & 7) << 7) | (j >> 7);
}
// r-major shared addressing for amplitude/slot index s.
__device__ __forceinline__ int ADDR(int s) { return ((s & 3) << 8) | (s >> 2); }
// GF(2)-linear bank swizzle (XORs strictly-higher bits into lower bits).
__device__ __forceinline__ int swz(int a) {
    return a ^ ((a >> 5) & 0xF) ^ ((a >> 1) & 8) ^ ((a >> 2) & 1);
}

__global__ __launch_bounds__(NTH, 5)
void qh_kernel(const float* __restrict__ c_kt,
               const float* __restrict__ dc_kt,
               const float* __restrict__ vqc,
               const float* __restrict__ wproj,
               const float* __restrict__ bproj,
               const float* __restrict__ lalpha,
               float* __restrict__ out)
{
    __shared__ float feat[NQ * FS];       // [k][t], padded stride
    __shared__ float2 bufA[DIM];          // exchange double-buffer A
    __shared__ float2 bufB[DIM];          // exchange double-buffer B
    __shared__ int lutA[NL][32], lutB[NL][32];  // swz(ADDR(sigma(Perm_l(.))))
    __shared__ float G[NG];
    __shared__ float Ssum[NQ];
    __shared__ float Jp[NPAIR];
    __shared__ float cth[NQ], sth[NQ], phh[NQ];
    __shared__ float thetaS[NQ], phiS[NQ];
    __shared__ float4 gmB[NL][NQ][2];     // [0]=(u00,u01), [1]=(u11,u10)
    __shared__ float wsh[NA][NQ];
    __shared__ float wred[8][4];
    // nibble tables: h1 = tid[7:4] (qubits 0-3), h2 = tid[3:0] (qubits 4-7)
    __shared__ float T1mag[16], T1ph[16], T1J[16], TA1[16], TB1[16];
    __shared__ float T2mag[16], T2ph[16], T2J[16], TA2[16], TB2[16];
    __shared__ float Rrow[4][16];          // cross-nibble J row sums
    __shared__ float W1[NA][16], W2[NA][16];  // epilogue +/- w sums

    const int b    = blockIdx.x;
    const int tid  = threadIdx.x;
    const int warp = tid >> 5;
    const int lane = tid & 31;

    const float* cb = c_kt  + (size_t)b * (NQ * TT);
    const float* db = dc_kt + (size_t)b * (NQ * TT);

    // ---- phase 1: stage inputs + build permutation LUTs (data-independent) ----
    for (int i = tid; i < NQ * TT; i += NTH) {
        int t = i / NQ, k = i - t * NQ;
        feat[k * FS + t] = fmaf(0.5f, db[i], cb[i]);   // conflict-free (stride 133)
    }
    if (tid < NQ) {
        thetaS[tid] = cb[(TT - 1) * NQ + tid];
        phiS[tid]   = db[(TT - 1) * NQ + tid];
    }
    if (tid >= 224 && tid < 224 + NA * NQ) {
        int i = tid - 224;
        wsh[i / NQ][i - (i / NQ) * NQ] = wproj[i];
    }
    if (tid < 192) {
        int l = tid / 64, k = tid & 63;
        int idx = (k < 32) ? k : ((k - 32) << 5);
        const int rng = l + 1;
        #pragma unroll
        for (int q = NQ - 1; q >= 0; q--) {
            int tgt = q + rng; if (tgt >= NQ) tgt -= NQ;
            if ((idx >> (NQ - 1 - q)) & 1) idx ^= 1 << (NQ - 1 - tgt);
        }
        int p = swz(ADDR(sigma(idx)));
        if (k < 32) lutA[l][k] = p; else lutB[l][k - 32] = p;
    }
    __syncthreads();

    // ---- phase 2: 55 Gram dots (+fused row sums), contiguous ranges, fi cached ----
    {
        const int lo = c_LO[warp], hi = c_LO[warp + 1];
        int cur_i = -1;
        float vi0=0.f, vi1=0.f, vi2=0.f, vi3=0.f;
        for (int tk = lo; tk < hi; tk++) {
            int i = c_TI[tk], j = c_TJ[tk];
            if (i != cur_i) {
                cur_i = i;
                const float* fi = feat + i * FS + lane;
                vi0 = fi[0]; vi1 = fi[32]; vi2 = fi[64]; vi3 = fi[96];
            }
            float s;
            if (j == i) {
                s = vi0*vi0 + vi1*vi1 + vi2*vi2 + vi3*vi3;
                float ss = vi0 + vi1 + vi2 + vi3;
                #pragma unroll
                for (int o = 16; o; o >>= 1) ss += __shfl_xor_sync(0xffffffffu, ss, o);
                if (lane == 0) Ssum[i] = ss;
            } else {
                const float* fj = feat + j * FS + lane;
                s = vi0*fj[0] + vi1*fj[32] + vi2*fj[64] + vi3*fj[96];
            }
            #pragma unroll
            for (int o = 16; o; o >>= 1) s += __shfl_xor_sync(0xffffffffu, s, o);
            if (lane == 0) G[tk] = s;
        }
    }
    __syncthreads();

    // ---- phase 3 (parallel sub-jobs) ----
    if (tid < NPAIR) {
        int i = c_PI[tid], j = c_PJ[tid];
        float Si = Ssum[i], Sj = Ssum[j];
        const float invT = 1.f / TT, invT1 = 1.f / (TT - 1);
        float vi = (G[c_OFF[i]] - Si * Si * invT) * invT1;
        float vj = (G[c_OFF[j]] - Sj * Sj * invT) * invT1;
        float si = fmaxf(sqrtf(vi), 1e-8f);
        float sj = fmaxf(sqrtf(vj), 1e-8f);
        float num = (G[c_OFF[i] + (j - i)] - Si * Sj * invT) * invT1;
        float rho = num / (si * sj);
        Jp[tid] = __tanhf(rho * __expf(lalpha[0]));
    } else if (tid >= 64 && tid < 64 + NQ) {
        int q = tid - 64;
        float sq, cq;
        __sincosf(0.5f * thetaS[q], &sq, &cq);
        cth[q] = cq; sth[q] = sq;
        phh[q] = 0.5f * phiS[q];
    } else if (tid >= 128 && tid < 128 + NL * NQ) {
        int idx = tid - 128;
        int l = idx / NQ, q = idx - l * NQ;
        float a  = vqc[idx * 3 + 0];
        float bb = vqc[idx * 3 + 1];
        float c  = vqc[idx * 3 + 2];
        float sb2, cb2; __sincosf(0.5f * bb, &sb2, &cb2);
        float apc = 0.5f * (a + c), amc = 0.5f * (a - c);
        float capc, sapc, camc, samc;
        __sincosf(apc, &sapc, &capc);
        __sincosf(amc, &samc, &camc);
        float2 u00 = make_float2( capc * cb2, -sapc * cb2);
        float2 u01 = make_float2(-camc * sb2, -samc * sb2);
        float2 u10 = make_float2( camc * sb2, -samc * sb2);
        float2 u11 = make_float2( capc * cb2,  sapc * cb2);
        if (l != 0) {
            // Fold preceding RY(theta/2), RZ(phi/2) into this layer's rot.
            float thq = 0.25f * thetaS[q], phq = 0.25f * phiS[q];
            float st, ct; __sincosf(thq, &st, &ct);
            float sp, cp; __sincosf(phq, &sp, &cp);
            float2 A00 = make_float2( cp * ct, -sp * ct);
            float2 A01 = make_float2(-cp * st,  sp * st);
            float2 A10 = make_float2( cp * st,  sp * st);
            float2 A11 = make_float2( cp * ct,  sp * ct);
            float2 v00 = cxadd(cxmul(u00, A00), cxmul(u01, A10));
            float2 v01 = cxadd(cxmul(u00, A01), cxmul(u01, A11));
            float2 v10 = cxadd(cxmul(u10, A00), cxmul(u11, A10));
            float2 v11 = cxadd(cxmul(u10, A01), cxmul(u11, A11));
            u00 = v00; u01 = v01; u10 = v10; u11 = v11;
        }
        gmB[l][q][0] = make_float4(u00.x, u00.y, u01.x, u01.y);
        gmB[l][q][1] = make_float4(u11.x, u11.y, u10.x, u10.y);
    }
    __syncthreads();

    // ---- phase 3.5: build nibble tables (needs Jp, cth/sth/phh, wsh) ----
    if (tid < 16) {
        // qubits 0..3; bit of q = (h >> (3-q)) & 1
        int h = tid;
        float m = 1.f, p = 0.f, jj = 0.f, aa = 0.f, bv = 0.f;
        #pragma unroll
        for (int q = 0; q < 4; q++) {
            bool bit = (h >> (3 - q)) & 1;
            m *= bit ? sth[q] : cth[q];
            p += bit ? phh[q] : -phh[q];
            float ja = Jp[idx45(q, 8)], jb = Jp[idx45(q, 9)];
            aa += bit ? ja : -ja;
            bv += bit ? jb : -jb;
        }
        #pragma unroll
        for (int i = 0; i < 3; i++)
            #pragma unroll
            for (int j2 = i + 1; j2 < 4; j2++) {
                bool si = (h >> (3 - i)) & 1, sj = (h >> (3 - j2)) & 1;
                float v = Jp[idx45(i, j2)];
                jj += (si ^ sj) ? v : -v;
            }
        T1mag[h] = m; T1ph[h] = p; T1J[h] = jj; TA1[h] = aa; TB1[h] = bv;
    } else if (tid < 32) {
        // qubits 4..7; bit of q = (h >> (7-q)) & 1
        int h = tid - 16;
        float m = 1.f, p = 0.f, jj = 0.f, aa = 0.f, bv = 0.f;
        #pragma unroll
        for (int q = 4; q < 8; q++) {
            bool bit = (h >> (7 - q)) & 1;
            m *= bit ? sth[q] : cth[q];
            p += bit ? phh[q] : -phh[q];
            float ja = Jp[idx45(q, 8)], jb = Jp[idx45(q, 9)];
            aa += bit ? ja : -ja;
            bv += bit ? jb : -jb;
        }
        #pragma unroll
        for (int i = 4; i < 7; i++)
            #pragma unroll
            for (int j2 = i + 1; j2 < 8; j2++) {
                bool si = (h >> (7 - i)) & 1, sj = (h >> (7 - j2)) & 1;
                float v = Jp[idx45(i, j2)];
                jj += (si ^ sj) ? v : -v;
            }
        T2mag[h] = m; T2ph[h] = p; T2J[h] = jj; TA2[h] = aa; TB2[h] = bv;
    } else if (tid < 96) {
        // cross-nibble rows: Rrow[i][h2] = sum_j (bit_j ? +J_ij : -J_ij), i in 0..3, j in 4..7
        int e = tid - 32;
        int i = e >> 4, h2 = e & 15;
        float r = 0.f;
        #pragma unroll
        for (int j2 = 4; j2 < 8; j2++) {
            bool bit = (h2 >> (7 - j2)) & 1;
            float v = Jp[idx45(i, j2)];
            r += bit ? v : -v;
        }
        Rrow[i][h2] = r;
    } else if (tid < 192) {
        // epilogue sign-weight tables
        int e = tid - 96;           // 0..95
        int half = e / 48;          // 0 -> W1 (k=0..3), 1 -> W2 (k=4..7)
        int rem = e - half * 48;
        int a = rem >> 4, h = rem & 15;
        float g = 0.f;
        #pragma unroll
        for (int k = 0; k < 4; k++) {
            int q = half * 4 + k;
            bool bit = (h >> (3 - k)) & 1;
            float w = wsh[a][q];
            g += bit ? -w : w;
        }
        if (half == 0) W1[a][h] = g; else W2[a][h] = g;
    }
    __syncthreads();

    // ===================== state in registers =====================
    // slot s = (tid<<2)|r.  qubit q in 0..7 <-> tid bit (7-q); q8 <-> r bit1, q9 <-> r bit0.
    float aR[4], aI[4];
    {
        const int h1 = tid >> 4, h2 = tid & 15;
        float magHi = T1mag[h1] * T2mag[h2];
        float phHi  = T1ph[h1] + T2ph[h2];
        float base  = T1J[h1] + T2J[h2];
        #pragma unroll
        for (int i = 0; i < 4; i++) {
            bool ti = (h1 >> (3 - i)) & 1;
            float rv = Rrow[i][h2];
            base += ti ? -rv : rv;
        }
        float A  = TA1[h1] + TA2[h2];
        float Bv = TB1[h1] + TB2[h2];
        float C = Jp[44];
        float c8 = cth[8], s8 = sth[8], c9 = cth[9], s9 = sth[9];
        float p8 = phh[8], p9 = phh[9];
        #pragma unroll
        for (int r = 0; r < 4; r++) {
            bool b8 = (r >> 1) & 1, b9 = r & 1;
            float mag = magHi * (b8 ? s8 : c8) * (b9 ? s9 : c9);
            float ph  = phHi + (b8 ? p8 : -p8) + (b9 ? p9 : -p9);
            float aJ  = base + (b8 ? -A : A) + (b9 ? -Bv : Bv) + ((b8 ^ b9) ? C : -C);
            ph = fmaf(0.5f * PI_F, aJ, ph);
            float sp, cp; __sincosf(ph, &sp, &cp);
            aR[r] = mag * cp; aI[r] = mag * sp;
        }
    }

    // Swizzled exchange address bases (computed once).
    const int ftid = swz(tid);  // store base: addr_r = ftid ^ cstS[r]
    int pbase;                  // gather-1 base: addr_r = fpb ^ cstG[r]
    {
        pbase = (((tid >> 5) & 3) << 8) | (tid & 0x1E) | ((tid & 1) << 7) | (tid >> 7);
    }
    const int fpb = swz(pbase);
    const int cstS[4] = {0x000, 0x108, 0x200, 0x308};   // swz(r<<8)
    const int cstG[4] = {0x00, 0x21, 0x42, 0x63};       // swz(r<<5)
    const int laIdxBase = (tid & 7) << 2;
    const int lbIdx = tid >> 3;

    #pragma unroll
    for (int l = 0; l < NL; l++) {
        // register gates q=9 (r bit0), q=8 (r bit1): reconstruct (u10,u11) by half-swap
        {
            float4 A = gmB[l][9][0], t = gmB[l][9][1];
            float4 B = make_float4(t.z, t.w, t.x, t.y);
            bf_pair(A, B, aR[0], aI[0], aR[1], aI[1]);
            bf_pair(A, B, aR[2], aI[2], aR[3], aI[3]);
        }
        {
            float4 A = gmB[l][8][0], t = gmB[l][8][1];
            float4 B = make_float4(t.z, t.w, t.x, t.y);
            bf_pair(A, B, aR[0], aI[0], aR[2], aI[2]);
            bf_pair(A, B, aR[1], aI[1], aR[3], aI[3]);
        }
        // lane gates q=7..3 (lane bit 7-q): single bit-indexed LDS.128
        #pragma unroll
        for (int q = 7; q >= 3; q--) {
            const int k = 7 - q;
            float4 U = gmB[l][q][(lane >> k) & 1];
            lane_gate(U, k, aR, aI);
        }

        // exchange to view B (buffer A): conflict-free store, swizzled gather
        #pragma unroll
        for (int r = 0; r < 4; r++)
            bufA[ftid ^ cstS[r]] = make_float2(aR[r], aI[r]);
        __syncthreads();
        #pragma unroll
        for (int r = 0; r < 4; r++) {
            float2 v = bufA[fpb ^ cstG[r]];
            aR[r] = v.x; aI[r] = v.y;
        }

        // view-B gates: q=2 -> r bit0, q=1 -> r bit1, q=0 -> lane bit0
        {
            float4 A = gmB[l][2][0], t = gmB[l][2][1];
            float4 B = make_float4(t.z, t.w, t.x, t.y);
            bf_pair(A, B, aR[0], aI[0], aR[1], aI[1]);
            bf_pair(A, B, aR[2], aI[2], aR[3], aI[3]);
        }
        {
            float4 A = gmB[l][1][0], t = gmB[l][1][1];
            float4 B = make_float4(t.z, t.w, t.x, t.y);
            bf_pair(A, B, aR[0], aI[0], aR[2], aI[2]);
            bf_pair(A, B, aR[1], aI[1], aR[3], aI[3]);
        }
        {
            float4 U = gmB[l][0][lane & 1];
            lane_gate(U, 0, aR, aI);
        }

        // exchange back + composed-CNOT permutation via linear LUT (buffer B)
        #pragma unroll
        for (int r = 0; r < 4; r++)
            bufB[ftid ^ cstS[r]] = make_float2(aR[r], aI[r]);
        __syncthreads();
        {
            int mb = lutB[l][lbIdx];
            #pragma unroll
            for (int r = 0; r < 4; r++) {
                float2 v = bufB[mb ^ lutA[l][laIdxBase | r]];
                aR[r] = v.x; aI[r] = v.y;
            }
        }
    }

    // ---- epilogue (table-based sign weights) ----
    {
        const int h1 = tid >> 4, h2 = tid & 15;
        float g0Hi = W1[0][h1] + W2[0][h2];
        float g1Hi = W1[1][h1] + W2[1][h2];
        float g2Hi = W1[2][h1] + W2[2][h2];
        float w08 = wsh[0][8], w09 = wsh[0][9];
        float w18 = wsh[1][8], w19 = wsh[1][9];
        float w28 = wsh[2][8], w29 = wsh[2][9];
        float acc0 = 0.f, acc1 = 0.f, acc2 = 0.f;
        #pragma unroll
        for (int r = 0; r < 4; r++) {
            bool b8 = (r >> 1) & 1, b9 = r & 1;
            float pr = aR[r]*aR[r] + aI[r]*aI[r];
            acc0 = fmaf(pr, g0Hi + (b8 ? -w08 : w08) + (b9 ? -w09 : w09), acc0);
            acc1 = fmaf(pr, g1Hi + (b8 ? -w18 : w18) + (b9 ? -w19 : w19), acc1);
            acc2 = fmaf(pr, g2Hi + (b8 ? -w28 : w28) + (b9 ? -w29 : w29), acc2);
        }
        #pragma unroll
        for (int o = 16; o; o >>= 1) {
            acc0 += __shfl_xor_sync(0xffffffffu, acc0, o);
            acc1 += __shfl_xor_sync(0xffffffffu, acc1, o);
            acc2 += __shfl_xor_sync(0xffffffffu, acc2, o);
        }
        if (lane == 0) {
            wred[warp][0] = acc0; wred[warp][1] = acc1; wred[warp][2] = acc2;
        }
    }
    __syncthreads();
    if (tid < NA) {
        float s = bproj[tid];
        #pragma unroll
        for (int w = 0; w < 8; w++) s += wred[w][tid];
        out[b * NA + tid] = s;
    }
}

extern "C" void kernel_launch(void* const* d_in, const int* in_sizes, int n_in,
                              void* d_out, int out_size) {
    const float* c_kt   = (const float*)d_in[0];
    const float* dc_kt  = (const float*)d_in[1];
    const float* vqc    = (const float*)d_in[2];
    const float* wproj  = (const float*)d_in[3];
    const float* bproj  = (const float*)d_in[4];
    const float* lalpha = (const float*)d_in[5];
    int B = in_sizes[0] / (NQ * TT);
    qh_kernel<<<B, NTH>>>(c_kt, dc_kt, vqc, wproj, bproj, lalpha, (float*)d_out);
}

// round 13
// speedup vs baseline: 3.7397x; 1.0004x over previous
#include <cuda_runtime.h>
#include <math.h>

#define NQ 10
#define DIM 1024
#define NPAIR 45
#define NG 55
#define TT 128
#define FS 133          // padded feat row stride (5k mod 32 distinct for k=0..9)
#define NTH 256
#define NL 3
#define NA 3
#define PI_F 3.14159265358979323846f

// Upper-triangle (i<j) pair indices, row-major: 45 pairs.
__constant__ int c_PI[NPAIR] = {0,0,0,0,0,0,0,0,0, 1,1,1,1,1,1,1,1, 2,2,2,2,2,2,2,
                                3,3,3,3,3,3, 4,4,4,4,4, 5,5,5,5, 6,6,6, 7,7, 8};
__constant__ int c_PJ[NPAIR] = {1,2,3,4,5,6,7,8,9, 2,3,4,5,6,7,8,9, 3,4,5,6,7,8,9,
                                4,5,6,7,8,9, 5,6,7,8,9, 6,7,8,9, 7,8,9, 8,9, 9};
// Gram tasks: all (i<=j) pairs incl diagonal, row-major: 55.
__constant__ int c_TI[NG] = {0,0,0,0,0,0,0,0,0,0, 1,1,1,1,1,1,1,1,1, 2,2,2,2,2,2,2,2,
                             3,3,3,3,3,3,3, 4,4,4,4,4,4, 5,5,5,5,5, 6,6,6,6, 7,7,7, 8,8, 9};
__constant__ int c_TJ[NG] = {0,1,2,3,4,5,6,7,8,9, 1,2,3,4,5,6,7,8,9, 2,3,4,5,6,7,8,9,
                             3,4,5,6,7,8,9, 4,5,6,7,8,9, 5,6,7,8,9, 6,7,8,9, 7,8,9, 8,9, 9};
// Offset of (i,i) within the 55-list.
__constant__ int c_OFF[NQ] = {0,10,19,27,34,40,45,49,52,54};
// Contiguous per-warp task ranges over the 55 Gram tasks.
__constant__ int c_LO[9] = {0,7,14,21,28,35,42,49,55};

__device__ __forceinline__ int idx45(int i, int j) {   // Jp index for pair (i<j)
    return i * 9 - ((i * (i + 1)) >> 1) + j - 1;
}

__device__ __forceinline__ float2 cxmul(float2 a, float2 b) {
    return make_float2(a.x*b.x - a.y*b.y, a.x*b.y + a.y*b.x);
}
__device__ __forceinline__ float2 cxadd(float2 a, float2 b) {
    return make_float2(a.x + b.x, a.y + b.y);
}

// SU(2) butterfly on one amplitude pair.
// U = (u00.x, u00.y, u01.x, u01.y); row 2 = (-conj(u01), conj(u00)) via sign folding.
__device__ __forceinline__ void bf_su2(float4 U,
                                       float& r0, float& i0, float& r1, float& i1) {
    float n0r =  U.x*r0 - U.y*i0 + U.z*r1 - U.w*i1;
    float n0i =  U.x*i0 + U.y*r0 + U.z*i1 + U.w*r1;
    float n1r = -U.z*r0 - U.w*i0 + U.x*r1 + U.y*i1;
    float n1i = -U.z*i0 + U.w*r0 + U.x*i1 - U.y*r1;
    r0 = n0r; i0 = n0i; r1 = n1r; i1 = n1i;
}

// Shuffle butterfly on lane bit k; SU(2) gate, bit-dependent signs folded once.
__device__ __forceinline__ void lane_gate_su2(float4 U, bool bit, int k,
                                              float aR[4], float aI[4]) {
    float sy = bit ? -U.y : U.y;   // row-select of u00 imag
    float sx = bit ? -U.z : U.z;   // row-select of u01 real
    #pragma unroll
    for (int r = 0; r < 4; r++) {
        float pr = __shfl_xor_sync(0xffffffffu, aR[r], 1 << k);
        float pi = __shfl_xor_sync(0xffffffffu, aI[r], 1 << k);
        float nr = U.x*aR[r] - sy*aI[r] + sx*pr - U.w*pi;
        float ni = U.x*aI[r] + sy*aR[r] + sx*pi + U.w*pr;
        aR[r] = nr; aI[r] = ni;
    }
}

// View-B map: swap amp bits [9:7] <-> slot bits [2:0] (involution).
__device__ __forceinline__ int sigma(int j) {
    return (j & 0x078) | ((j & 7) << 7) | (j >> 7);
}
// r-major shared addressing for amplitude/slot index s.
__device__ __forceinline__ int ADDR(int s) { return ((s & 3) << 8) | (s >> 2); }
// GF(2)-linear bank swizzle (XORs strictly-higher bits into lower bits).
__device__ __forceinline__ int swz(int a) {
    return a ^ ((a >> 5) & 0xF) ^ ((a >> 1) & 8) ^ ((a >> 2) & 1);
}

__global__ __launch_bounds__(NTH, 6)
void qh_kernel(const float* __restrict__ c_kt,
               const float* __restrict__ dc_kt,
               const float* __restrict__ vqc,
               const float* __restrict__ wproj,
               const float* __restrict__ bproj,
               const float* __restrict__ lalpha,
               float* __restrict__ out)
{
    __shared__ float feat[NQ * FS];       // [k][t], padded stride
    __shared__ float2 bufA[DIM];          // exchange double-buffer A
    __shared__ float2 bufB[DIM];          // exchange double-buffer B
    __shared__ int lutA[NL][32], lutB[NL][32];  // swz(ADDR(sigma(Perm_l(.))))
    __shared__ float G[NG];
    __shared__ float Ssum[NQ];
    __shared__ float Jp[NPAIR];
    __shared__ float cth[NQ], sth[NQ], phh[NQ];
    __shared__ float thetaS[NQ], phiS[NQ];
    __shared__ float4 gm2[NL][NQ];        // SU(2) gate: (u00.x,u00.y,u01.x,u01.y)
    __shared__ float wsh[NA][NQ];
    __shared__ float wred[8][4];
    // nibble tables: h1 = tid[7:4] (qubits 0-3), h2 = tid[3:0] (qubits 4-7)
    __shared__ float T1mag[16], T1ph[16], T1J[16], TA1[16], TB1[16];
    __shared__ float T2mag[16], T2ph[16], T2J[16], TA2[16], TB2[16];
    __shared__ float Rrow[4][16];          // cross-nibble J row sums
    __shared__ float W1[NA][16], W2[NA][16];  // epilogue +/- w sums

    const int b    = blockIdx.x;
    const int tid  = threadIdx.x;
    const int warp = tid >> 5;
    const int lane = tid & 31;

    const float* cb = c_kt  + (size_t)b * (NQ * TT);
    const float* db = dc_kt + (size_t)b * (NQ * TT);

    // ---- phase 1: stage inputs + build permutation LUTs (data-independent) ----
    for (int i = tid; i < NQ * TT; i += NTH) {
        int t = i / NQ, k = i - t * NQ;
        feat[k * FS + t] = fmaf(0.5f, db[i], cb[i]);   // conflict-free (stride 133)
    }
    if (tid < NQ) {
        thetaS[tid] = cb[(TT - 1) * NQ + tid];
        phiS[tid]   = db[(TT - 1) * NQ + tid];
    }
    if (tid >= 224 && tid < 224 + NA * NQ) {
        int i = tid - 224;
        wsh[i / NQ][i - (i / NQ) * NQ] = wproj[i];
    }
    if (tid < 192) {
        int l = tid / 64, k = tid & 63;
        int idx = (k < 32) ? k : ((k - 32) << 5);
        const int rng = l + 1;
        #pragma unroll
        for (int q = NQ - 1; q >= 0; q--) {
            int tgt = q + rng; if (tgt >= NQ) tgt -= NQ;
            if ((idx >> (NQ - 1 - q)) & 1) idx ^= 1 << (NQ - 1 - tgt);
        }
        int p = swz(ADDR(sigma(idx)));
        if (k < 32) lutA[l][k] = p; else lutB[l][k - 32] = p;
    }
    __syncthreads();

    // ---- phase 2: 55 Gram dots (+fused row sums), contiguous ranges, fi cached ----
    {
        const int lo = c_LO[warp], hi = c_LO[warp + 1];
        int cur_i = -1;
        float vi0=0.f, vi1=0.f, vi2=0.f, vi3=0.f;
        for (int tk = lo; tk < hi; tk++) {
            int i = c_TI[tk], j = c_TJ[tk];
            if (i != cur_i) {
                cur_i = i;
                const float* fi = feat + i * FS + lane;
                vi0 = fi[0]; vi1 = fi[32]; vi2 = fi[64]; vi3 = fi[96];
            }
            float s;
            if (j == i) {
                s = vi0*vi0 + vi1*vi1 + vi2*vi2 + vi3*vi3;
                float ss = vi0 + vi1 + vi2 + vi3;
                #pragma unroll
                for (int o = 16; o; o >>= 1) ss += __shfl_xor_sync(0xffffffffu, ss, o);
                if (lane == 0) Ssum[i] = ss;
            } else {
                const float* fj = feat + j * FS + lane;
                s = vi0*fj[0] + vi1*fj[32] + vi2*fj[64] + vi3*fj[96];
            }
            #pragma unroll
            for (int o = 16; o; o >>= 1) s += __shfl_xor_sync(0xffffffffu, s, o);
            if (lane == 0) G[tk] = s;
        }
    }
    __syncthreads();

    // ---- phase 3 (parallel sub-jobs) ----
    if (tid < NPAIR) {
        int i = c_PI[tid], j = c_PJ[tid];
        float Si = Ssum[i], Sj = Ssum[j];
        const float invT = 1.f / TT, invT1 = 1.f / (TT - 1);
        float vi = (G[c_OFF[i]] - Si * Si * invT) * invT1;
        float vj = (G[c_OFF[j]] - Sj * Sj * invT) * invT1;
        float si = fmaxf(sqrtf(vi), 1e-8f);
        float sj = fmaxf(sqrtf(vj), 1e-8f);
        float num = (G[c_OFF[i] + (j - i)] - Si * Sj * invT) * invT1;
        float rho = num / (si * sj);
        Jp[tid] = __tanhf(rho * __expf(lalpha[0]));
    } else if (tid >= 64 && tid < 64 + NQ) {
        int q = tid - 64;
        float sq, cq;
        __sincosf(0.5f * thetaS[q], &sq, &cq);
        cth[q] = cq; sth[q] = sq;
        phh[q] = 0.5f * phiS[q];
    } else if (tid >= 128 && tid < 128 + NL * NQ) {
        int idx = tid - 128;
        int l = idx / NQ, q = idx - l * NQ;
        float a  = vqc[idx * 3 + 0];
        float bb = vqc[idx * 3 + 1];
        float c  = vqc[idx * 3 + 2];
        float sb2, cb2; __sincosf(0.5f * bb, &sb2, &cb2);
        float apc = 0.5f * (a + c), amc = 0.5f * (a - c);
        float capc, sapc, camc, samc;
        __sincosf(apc, &sapc, &capc);
        __sincosf(amc, &samc, &camc);
        float2 u00 = make_float2( capc * cb2, -sapc * cb2);
        float2 u01 = make_float2(-camc * sb2, -samc * sb2);
        if (l != 0) {
            // Fold preceding RY(theta/2), RZ(phi/2) into this layer's rot.
            // A is SU(2): A10 = -conj(A01), A11 = conj(A00).
            float thq = 0.25f * thetaS[q], phq = 0.25f * phiS[q];
            float st, ct; __sincosf(thq, &st, &ct);
            float sp, cp; __sincosf(phq, &sp, &cp);
            float2 A00 = make_float2( cp * ct, -sp * ct);
            float2 A01 = make_float2(-cp * st,  sp * st);
            float2 A10 = make_float2(-A01.x,  A01.y);
            float2 A11 = make_float2( A00.x, -A00.y);
            float2 v00 = cxadd(cxmul(u00, A00), cxmul(u01, A10));
            float2 v01 = cxadd(cxmul(u00, A01), cxmul(u01, A11));
            u00 = v00; u01 = v01;
        }
        gm2[l][q] = make_float4(u00.x, u00.y, u01.x, u01.y);
    }
    __syncthreads();

    // ---- phase 3.5: build nibble tables (needs Jp, cth/sth/phh, wsh) ----
    if (tid < 16) {
        // qubits 0..3; bit of q = (h >> (3-q)) & 1
        int h = tid;
        float m = 1.f, p = 0.f, jj = 0.f, aa = 0.f, bv = 0.f;
        #pragma unroll
        for (int q = 0; q < 4; q++) {
            bool bit = (h >> (3 - q)) & 1;
            m *= bit ? sth[q] : cth[q];
            p += bit ? phh[q] : -phh[q];
            float ja = Jp[idx45(q, 8)], jb = Jp[idx45(q, 9)];
            aa += bit ? ja : -ja;
            bv += bit ? jb : -jb;
        }
        #pragma unroll
        for (int i = 0; i < 3; i++)
            #pragma unroll
            for (int j2 = i + 1; j2 < 4; j2++) {
                bool si = (h >> (3 - i)) & 1, sj = (h >> (3 - j2)) & 1;
                float v = Jp[idx45(i, j2)];
                jj += (si ^ sj) ? v : -v;
            }
        T1mag[h] = m; T1ph[h] = p; T1J[h] = jj; TA1[h] = aa; TB1[h] = bv;
    } else if (tid < 32) {
        // qubits 4..7; bit of q = (h >> (7-q)) & 1
        int h = tid - 16;
        float m = 1.f, p = 0.f, jj = 0.f, aa = 0.f, bv = 0.f;
        #pragma unroll
        for (int q = 4; q < 8; q++) {
            bool bit = (h >> (7 - q)) & 1;
            m *= bit ? sth[q] : cth[q];
            p += bit ? phh[q] : -phh[q];
            float ja = Jp[idx45(q, 8)], jb = Jp[idx45(q, 9)];
            aa += bit ? ja : -ja;
            bv += bit ? jb : -jb;
        }
        #pragma unroll
        for (int i = 4; i < 7; i++)
            #pragma unroll
            for (int j2 = i + 1; j2 < 8; j2++) {
                bool si = (h >> (7 - i)) & 1, sj = (h >> (7 - j2)) & 1;
                float v = Jp[idx45(i, j2)];
                jj += (si ^ sj) ? v : -v;
            }
        T2mag[h] = m; T2ph[h] = p; T2J[h] = jj; TA2[h] = aa; TB2[h] = bv;
    } else if (tid < 96) {
        // cross-nibble rows: Rrow[i][h2] = sum_j (bit_j ? +J_ij : -J_ij), i in 0..3, j in 4..7
        int e = tid - 32;
        int i = e >> 4, h2 = e & 15;
        float r = 0.f;
        #pragma unroll
        for (int j2 = 4; j2 < 8; j2++) {
            bool bit = (h2 >> (7 - j2)) & 1;
            float v = Jp[idx45(i, j2)];
            r += bit ? v : -v;
        }
        Rrow[i][h2] = r;
    } else if (tid < 192) {
        // epilogue sign-weight tables
        int e = tid - 96;           // 0..95
        int half = e / 48;          // 0 -> W1 (k=0..3), 1 -> W2 (k=4..7)
        int rem = e - half * 48;
        int a = rem >> 4, h = rem & 15;
        float g = 0.f;
        #pragma unroll
        for (int k = 0; k < 4; k++) {
            int q = half * 4 + k;
            bool bit = (h >> (3 - k)) & 1;
            float w = wsh[a][q];
            g += bit ? -w : w;
        }
        if (half == 0) W1[a][h] = g; else W2[a][h] = g;
    }
    __syncthreads();

    // ===================== state in registers =====================
    // slot s = (tid<<2)|r.  qubit q in 0..7 <-> tid bit (7-q); q8 <-> r bit1, q9 <-> r bit0.
    float aR[4], aI[4];
    {
        const int h1 = tid >> 4, h2 = tid & 15;
        float magHi = T1mag[h1] * T2mag[h2];
        float phHi  = T1ph[h1] + T2ph[h2];
        float base  = T1J[h1] + T2J[h2];
        #pragma unroll
        for (int i = 0; i < 4; i++) {
            bool ti = (h1 >> (3 - i)) & 1;
            float rv = Rrow[i][h2];
            base += ti ? -rv : rv;
        }
        float A  = TA1[h1] + TA2[h2];
        float Bv = TB1[h1] + TB2[h2];
        float C = Jp[44];
        float c8 = cth[8], s8 = sth[8], c9 = cth[9], s9 = sth[9];
        float p8 = phh[8], p9 = phh[9];
        #pragma unroll
        for (int r = 0; r < 4; r++) {
            bool b8 = (r >> 1) & 1, b9 = r & 1;
            float mag = magHi * (b8 ? s8 : c8) * (b9 ? s9 : c9);
            float ph  = phHi + (b8 ? p8 : -p8) + (b9 ? p9 : -p9);
            float aJ  = base + (b8 ? -A : A) + (b9 ? -Bv : Bv) + ((b8 ^ b9) ? C : -C);
            ph = fmaf(0.5f * PI_F, aJ, ph);
            float sp, cp; __sincosf(ph, &sp, &cp);
            aR[r] = mag * cp; aI[r] = mag * sp;
        }
    }

    // Swizzled exchange address bases (computed once).
    const int ftid = swz(tid);  // store base: addr_r = ftid ^ cstS[r]
    int pbase;                  // gather-1 base: addr_r = fpb ^ cstG[r]
    {
        pbase = (((tid >> 5) & 3) << 8) | (tid & 0x1E) | ((tid & 1) << 7) | (tid >> 7);
    }
    const int fpb = swz(pbase);
    const int cstS[4] = {0x000, 0x108, 0x200, 0x308};   // swz(r<<8)
    const int cstG[4] = {0x00, 0x21, 0x42, 0x63};       // swz(r<<5)
    const int laIdxBase = (tid & 7) << 2;
    const int lbIdx = tid >> 3;

    #pragma unroll
    for (int l = 0; l < NL; l++) {
        // register gates q=9 (r bit0), q=8 (r bit1)
        {
            float4 U = gm2[l][9];
            bf_su2(U, aR[0], aI[0], aR[1], aI[1]);
            bf_su2(U, aR[2], aI[2], aR[3], aI[3]);
        }
        {
            float4 U = gm2[l][8];
            bf_su2(U, aR[0], aI[0], aR[2], aI[2]);
            bf_su2(U, aR[1], aI[1], aR[3], aI[3]);
        }
        // lane gates q=7..3 (lane bit 7-q): broadcast LDS.128 + sign fold
        #pragma unroll
        for (int q = 7; q >= 3; q--) {
            const int k = 7 - q;
            lane_gate_su2(gm2[l][q], (lane >> k) & 1, k, aR, aI);
        }

        // exchange to view B (buffer A): conflict-free store, swizzled gather
        #pragma unroll
        for (int r = 0; r < 4; r++)
            bufA[ftid ^ cstS[r]] = make_float2(aR[r], aI[r]);
        __syncthreads();
        #pragma unroll
        for (int r = 0; r < 4; r++) {
            float2 v = bufA[fpb ^ cstG[r]];
            aR[r] = v.x; aI[r] = v.y;
        }

        // view-B gates: q=2 -> r bit0, q=1 -> r bit1, q=0 -> lane bit0
        {
            float4 U = gm2[l][2];
            bf_su2(U, aR[0], aI[0], aR[1], aI[1]);
            bf_su2(U, aR[2], aI[2], aR[3], aI[3]);
        }
        {
            float4 U = gm2[l][1];
            bf_su2(U, aR[0], aI[0], aR[2], aI[2]);
            bf_su2(U, aR[1], aI[1], aR[3], aI[3]);
        }
        lane_gate_su2(gm2[l][0], lane & 1, 0, aR, aI);

        // exchange back + composed-CNOT permutation via linear LUT (buffer B)
        #pragma unroll
        for (int r = 0; r < 4; r++)
            bufB[ftid ^ cstS[r]] = make_float2(aR[r], aI[r]);
        __syncthreads();
        {
            int mb = lutB[l][lbIdx];
            #pragma unroll
            for (int r = 0; r < 4; r++) {
                float2 v = bufB[mb ^ lutA[l][laIdxBase | r]];
                aR[r] = v.x; aI[r] = v.y;
            }
        }
    }

    // ---- epilogue (table-based sign weights) ----
    {
        const int h1 = tid >> 4, h2 = tid & 15;
        float g0Hi = W1[0][h1] + W2[0][h2];
        float g1Hi = W1[1][h1] + W2[1][h2];
        float g2Hi = W1[2][h1] + W2[2][h2];
        float w08 = wsh[0][8], w09 = wsh[0][9];
        float w18 = wsh[1][8], w19 = wsh[1][9];
        float w28 = wsh[2][8], w29 = wsh[2][9];
        float acc0 = 0.f, acc1 = 0.f, acc2 = 0.f;
        #pragma unroll
        for (int r = 0; r < 4; r++) {
            bool b8 = (r >> 1) & 1, b9 = r & 1;
            float pr = aR[r]*aR[r] + aI[r]*aI[r];
            acc0 = fmaf(pr, g0Hi + (b8 ? -w08 : w08) + (b9 ? -w09 : w09), acc0);
            acc1 = fmaf(pr, g1Hi + (b8 ? -w18 : w18) + (b9 ? -w19 : w19), acc1);
            acc2 = fmaf(pr, g2Hi + (b8 ? -w28 : w28) + (b9 ? -w29 : w29), acc2);
        }
        #pragma unroll
        for (int o = 16; o; o >>= 1) {
            acc0 += __shfl_xor_sync(0xffffffffu, acc0, o);
            acc1 += __shfl_xor_sync(0xffffffffu, acc1, o);
            acc2 += __shfl_xor_sync(0xffffffffu, acc2, o);
        }
        if (lane == 0) {
            wred[warp][0] = acc0; wred[warp][1] = acc1; wred[warp][2] = acc2;
        }
    }
    __syncthreads();
    if (tid < NA) {
        float s = bproj[tid];
        #pragma unroll
        for (int w = 0; w < 8; w++) s += wred[w][tid];
        out[b * NA + tid] = s;
    }
}

extern "C" void kernel_launch(void* const* d_in, const int* in_sizes, int n_in,
                              void* d_out, int out_size) {
    const float* c_kt   = (const float*)d_in[0];
    const float* dc_kt  = (const float*)d_in[1];
    const float* vqc    = (const float*)d_in[2];
    const float* wproj  = (const float*)d_in[3];
    const float* bproj  = (const float*)d_in[4];
    const float* lalpha = (const float*)d_in[5];
    int B = in_sizes[0] / (NQ * TT);
    qh_kernel<<<B, NTH>>>(c_kt, dc_kt, vqc, wproj, bproj, lalpha, (float*)d_out);
}